// round 4
// baseline (speedup 1.0000x reference)
#include <cuda_runtime.h>
#include <stdint.h>

// SymmetricRBM: B=65536 independent Gibbs chains, N=64 visible, ALPHA=4 hidden groups,
// circulant weights from kernel[4][64]. One warp per sample; binary states as 64-bit masks.

#define NV      64
#define ALPHA   4
#define BATCH   65536
#define KSTEPS  10
#define WPB     8              // warps per block
#define NBLK    (BATCH / WPB)  // 8192 blocks

struct GibbsKeys {
    uint32_t kh0[KSTEPS], kh1[KSTEPS];  // hidden-sample keys per step
    uint32_t kv0[KSTEPS], kv1[KSTEPS];  // visible-sample keys per step
};

__device__ double g_partials[NBLK];

// ---------------- Threefry-2x32 (20 rounds), JAX-compatible ----------------

__device__ __host__ __forceinline__ uint32_t rotl32(uint32_t x, int r) {
    return (x << r) | (x >> (32 - r));
}

// Full threefry with both counter words, both outputs (host key-schedule use).
__host__ static void tf2x32_host(uint32_t k0, uint32_t k1, uint32_t c0, uint32_t c1,
                                 uint32_t* o0, uint32_t* o1) {
    uint32_t ks2 = k0 ^ k1 ^ 0x1BD11BDAu;
    uint32_t x0 = c0 + k0, x1 = c1 + k1;
#define R4A  x0+=x1; x1=rotl32(x1,13); x1^=x0; x0+=x1; x1=rotl32(x1,15); x1^=x0; \
             x0+=x1; x1=rotl32(x1,26); x1^=x0; x0+=x1; x1=rotl32(x1, 6); x1^=x0;
#define R4B  x0+=x1; x1=rotl32(x1,17); x1^=x0; x0+=x1; x1=rotl32(x1,29); x1^=x0; \
             x0+=x1; x1=rotl32(x1,16); x1^=x0; x0+=x1; x1=rotl32(x1,24); x1^=x0;
    R4A; x0 += k1;  x1 += ks2 + 1u;
    R4B; x0 += ks2; x1 += k0  + 2u;
    R4A; x0 += k0;  x1 += k1  + 3u;
    R4B; x0 += k1;  x1 += ks2 + 4u;
    R4A; x0 += ks2; x1 += k0  + 5u;
    *o0 = x0; *o1 = x1;
}

// Device: counter hi word is always 0 here (all sizes < 2^32); JAX partitionable
// random_bits returns x0 ^ x1.
__device__ __forceinline__ uint32_t tf_bits(uint32_t k0, uint32_t k1, uint32_t ctr_lo) {
    uint32_t ks2 = k0 ^ k1 ^ 0x1BD11BDAu;
    uint32_t x0 = k0;            // 0 + k0
    uint32_t x1 = ctr_lo + k1;
    R4A; x0 += k1;  x1 += ks2 + 1u;
    R4B; x0 += ks2; x1 += k0  + 2u;
    R4A; x0 += k0;  x1 += k1  + 3u;
    R4B; x0 += k1;  x1 += ks2 + 4u;
    R4A; x0 += ks2; x1 += k0  + 5u;
    return x0 ^ x1;
}
#undef R4A
#undef R4B

// JAX uniform [0,1): bitcast(bits>>9 | 0x3f800000) - 1.0f
__device__ __forceinline__ float u01(uint32_t bits) {
    return __uint_as_float((bits >> 9) | 0x3f800000u) - 1.0f;
}

// ---------------- wv: circulant forward, sparse over set bits of V ----------------
// wv[a,i] = sum_{j in bits(V)} k[a, (j - i) & 63]; lane handles i=lane and i=lane+32.
__device__ __forceinline__ void compute_wv(unsigned long long m, int lane,
                                           const float* __restrict__ ksh, float* w) {
#pragma unroll
    for (int q = 0; q < 2 * ALPHA; q++) w[q] = 0.0f;
    while (m) {
        int j = __ffsll((long long)m) - 1;
        m &= m - 1ull;
        int d  = (j - lane) & 63;
        int d2 = d ^ 32;
#pragma unroll
        for (int a = 0; a < ALPHA; a++) {
            w[a * 2 + 0] += ksh[a * NV + d];
            w[a * 2 + 1] += ksh[a * NV + d2];
        }
    }
}

__device__ __forceinline__ float softplus_sum(const float* w, const float* cc) {
    float s = 0.0f;
#pragma unroll
    for (int a = 0; a < ALPHA; a++) {
#pragma unroll
        for (int hh = 0; hh < 2; hh++) {
            float z = w[a * 2 + hh] + cc[a];
            s += fmaxf(z, 0.0f) + log1pf(__expf(-fabsf(z)));
        }
    }
    return s;
}

__device__ __forceinline__ float sigmoidf(float z) {
    return __fdividef(1.0f, 1.0f + __expf(-z));
}

// ---------------- main kernel: one warp per batch sample ----------------

__global__ void __launch_bounds__(WPB * 32)
rbm_kernel(const float* __restrict__ v_data, const float* __restrict__ kern,
           const float* __restrict__ bsc, const float* __restrict__ cvec,
           GibbsKeys keys) {
    __shared__ float  ksh[ALPHA * NV];
    __shared__ double wsum[WPB];

    const int tid = threadIdx.x;
    if (tid < ALPHA * NV) ksh[tid] = kern[tid];
    __syncthreads();

    const int lane = tid & 31;
    const int wid  = tid >> 5;
    const int b    = blockIdx.x * WPB + wid;

    const float bS = __ldg(bsc);
    float cc[ALPHA];
#pragma unroll
    for (int a = 0; a < ALPHA; a++) cc[a] = __ldg(cvec + a);

    // Load binary visible data, pack into a warp-uniform 64-bit mask.
    const float va = v_data[b * NV + lane];
    const float vb = v_data[b * NV + 32 + lane];
    unsigned long long V =
        (unsigned long long)__ballot_sync(0xffffffffu, va > 0.5f) |
        ((unsigned long long)__ballot_sync(0xffffffffu, vb > 0.5f) << 32);
    const unsigned long long Vdata = V;

    float w[2 * ALPHA];

    // free-energy softplus part for v_data
    compute_wv(Vdata, lane, ksh, w);
    const float sp_d = softplus_sum(w, cc);

    // ---------------- Gibbs chain ----------------
    for (int t = 0; t < KSTEPS; t++) {
        compute_wv(V, lane, ksh, w);

        const uint32_t kh0 = keys.kh0[t], kh1 = keys.kh1[t];
        unsigned long long H[ALPHA];
#pragma unroll
        for (int a = 0; a < ALPHA; a++) {
            const uint32_t mbase = (uint32_t)b * (ALPHA * NV) + (uint32_t)(a * NV) + (uint32_t)lane;
            float p0 = sigmoidf(w[a * 2 + 0] + cc[a]);
            float p1 = sigmoidf(w[a * 2 + 1] + cc[a]);
            int h0 = u01(tf_bits(kh0, kh1, mbase))       < p0;
            int h1 = u01(tf_bits(kh0, kh1, mbase + 32u)) < p1;
            H[a] = (unsigned long long)__ballot_sync(0xffffffffu, h0) |
                   ((unsigned long long)__ballot_sync(0xffffffffu, h1) << 32);
        }

        // wh[i] = sum_a sum_{m in bits(H[a])} k[a, (i-1-m) & 63]
        float wh0 = 0.0f, wh1 = 0.0f;
#pragma unroll
        for (int a = 0; a < ALPHA; a++) {
            unsigned long long m = H[a];
            const float* ka = ksh + a * NV;
            while (m) {
                int j = __ffsll((long long)m) - 1;
                m &= m - 1ull;
                int d = (lane - 1 - j) & 63;
                wh0 += ka[d];
                wh1 += ka[d ^ 32];
            }
        }

        const uint32_t kv0 = keys.kv0[t], kv1 = keys.kv1[t];
        const uint32_t mv  = (uint32_t)b * NV + (uint32_t)lane;
        float q0 = sigmoidf(wh0 + bS);
        float q1 = sigmoidf(wh1 + bS);
        int n0 = u01(tf_bits(kv0, kv1, mv))       < q0;
        int n1 = u01(tf_bits(kv0, kv1, mv + 32u)) < q1;
        V = (unsigned long long)__ballot_sync(0xffffffffu, n0) |
            ((unsigned long long)__ballot_sync(0xffffffffu, n1) << 32);
    }

    // free-energy softplus part for v_model
    compute_wv(V, lane, ksh, w);
    const float sp_m = softplus_sum(w, cc);

    // fe_data - fe_model = bS*(S_m - S_d) + (SP_m - SP_d)
    float x = sp_m - sp_d;
#pragma unroll
    for (int off = 16; off; off >>= 1) x += __shfl_xor_sync(0xffffffffu, x, off);

    if (lane == 0) {
        x += bS * (float)(__popcll(V) - __popcll(Vdata));
        wsum[wid] = (double)x;
    }
    __syncthreads();
    if (tid == 0) {
        double s = 0.0;
#pragma unroll
        for (int i = 0; i < WPB; i++) s += wsum[i];
        g_partials[blockIdx.x] = s;
    }
}

// ---------------- deterministic final reduction ----------------

__global__ void __launch_bounds__(256)
reduce_kernel(float* __restrict__ out) {
    __shared__ double sh[256];
    const int tid = threadIdx.x;
    double s = 0.0;
    for (int i = tid; i < NBLK; i += 256) s += g_partials[i];  // fixed order
    sh[tid] = s;
    __syncthreads();
    for (int off = 128; off; off >>= 1) {
        if (tid < off) sh[tid] += sh[tid + off];
        __syncthreads();
    }
    if (tid == 0) out[0] = (float)(sh[0] / (double)BATCH);
}

// ---------------- launch ----------------

extern "C" void kernel_launch(void* const* d_in, const int* in_sizes, int n_in,
                              void* d_out, int out_size) {
    (void)in_sizes; (void)n_in; (void)out_size;
    const float* v_data = (const float*)d_in[0];
    const float* kern   = (const float*)d_in[1];
    const float* bsc    = (const float*)d_in[2];
    const float* cvec   = (const float*)d_in[3];

    // Host-side JAX key schedule: key(42) = (0,42); fold-like split(k,3):
    // keys[i] = threefry(k, (0, i));  k,kh,kv = keys[0],keys[1],keys[2].
    GibbsKeys keys;
    uint32_t k0 = 0u, k1 = 42u;
    for (int t = 0; t < KSTEPS; t++) {
        uint32_t n0, n1, h0, h1, w0, w1;
        tf2x32_host(k0, k1, 0u, 0u, &n0, &n1);
        tf2x32_host(k0, k1, 0u, 1u, &h0, &h1);
        tf2x32_host(k0, k1, 0u, 2u, &w0, &w1);
        keys.kh0[t] = h0; keys.kh1[t] = h1;
        keys.kv0[t] = w0; keys.kv1[t] = w1;
        k0 = n0; k1 = n1;
    }

    rbm_kernel<<<NBLK, WPB * 32>>>(v_data, kern, bsc, cvec, keys);
    reduce_kernel<<<1, 256>>>((float*)d_out);
}

// round 5
// speedup vs baseline: 2.3538x; 2.3538x over previous
#include <cuda_runtime.h>
#include <stdint.h>

// SymmetricRBM: B=65536 independent Gibbs chains, N=64 visible, ALPHA=4 hidden groups,
// circulant weights from kernel[4][64]. One warp per sample; binary states as u32-pair masks.
//
// Key structure: wh depends on H only through 8-bit pair-signatures, and the weight
// kernel is launch-constant -> precompute T[256][64] float2 in shared (128KB) once per
// block; the wh inner loop collapses to 32 dense LDS.64+2FADD iterations.

#define NV      64
#define ALPHA   4
#define BATCH   65536
#define KSTEPS  10
#define TPB     1024
#define WPB     32             // warps (=samples) per block
#define NBLK    (BATCH / WPB)  // 2048 blocks

// dynamic smem layout
#define T_BYTES    (256 * 64 * 8)            // float2 T[256][64]   = 131072
#define KT4_OFF    T_BYTES
#define KT4_BYTES  (64 * 16)                 // float4 kT4[64]      = 1024
#define W_OFF      (KT4_OFF + KT4_BYTES)
#define W_BYTES    (16 * 64 * 4)             // float  W[16][64]    = 4096
#define WSUM_OFF   (W_OFF + W_BYTES)
#define WSUM_BYTES (WPB * 8)
#define SMEM_BYTES (WSUM_OFF + WSUM_BYTES)   // 136448

struct GibbsKeys {
    uint32_t kh0[KSTEPS], kh1[KSTEPS];
    uint32_t kv0[KSTEPS], kv1[KSTEPS];
};

__device__ double g_partials[NBLK];

// ---------------- Threefry-2x32 (20 rounds), JAX-compatible ----------------

__device__ __host__ __forceinline__ uint32_t rotl32(uint32_t x, int r) {
    return (x << r) | (x >> (32 - r));
}

__host__ static void tf2x32_host(uint32_t k0, uint32_t k1, uint32_t c0, uint32_t c1,
                                 uint32_t* o0, uint32_t* o1) {
    uint32_t ks2 = k0 ^ k1 ^ 0x1BD11BDAu;
    uint32_t x0 = c0 + k0, x1 = c1 + k1;
#define R4A  x0+=x1; x1=rotl32(x1,13); x1^=x0; x0+=x1; x1=rotl32(x1,15); x1^=x0; \
             x0+=x1; x1=rotl32(x1,26); x1^=x0; x0+=x1; x1=rotl32(x1, 6); x1^=x0;
#define R4B  x0+=x1; x1=rotl32(x1,17); x1^=x0; x0+=x1; x1=rotl32(x1,29); x1^=x0; \
             x0+=x1; x1=rotl32(x1,16); x1^=x0; x0+=x1; x1=rotl32(x1,24); x1^=x0;
    R4A; x0 += k1;  x1 += ks2 + 1u;
    R4B; x0 += ks2; x1 += k0  + 2u;
    R4A; x0 += k0;  x1 += k1  + 3u;
    R4B; x0 += k1;  x1 += ks2 + 4u;
    R4A; x0 += ks2; x1 += k0  + 5u;
    *o0 = x0; *o1 = x1;
}

// device: counter hi word always 0; JAX partitionable random_bits -> x0 ^ x1
__device__ __forceinline__ uint32_t tf_bits(uint32_t k0, uint32_t k1, uint32_t ctr_lo) {
    uint32_t ks2 = k0 ^ k1 ^ 0x1BD11BDAu;
    uint32_t x0 = k0;
    uint32_t x1 = ctr_lo + k1;
    R4A; x0 += k1;  x1 += ks2 + 1u;
    R4B; x0 += ks2; x1 += k0  + 2u;
    R4A; x0 += k0;  x1 += k1  + 3u;
    R4B; x0 += k1;  x1 += ks2 + 4u;
    R4A; x0 += ks2; x1 += k0  + 5u;
    return x0 ^ x1;
}
#undef R4A
#undef R4B

__device__ __forceinline__ float u01(uint32_t bits) {
    return __uint_as_float((bits >> 9) | 0x3f800000u) - 1.0f;
}

__device__ __forceinline__ float sigmoidf(float z) {
    return __fdividef(1.0f, 1.0f + __expf(-z));
}

// ---------------- wv: circulant forward, sparse over set bits, LDS.128 ----------------
// wv[a,lane] and wv[a,lane+32]; kT4[d] = {k0[d],k1[d],k2[d],k3[d]}
__device__ __forceinline__ void compute_wv(uint32_t lo, uint32_t hi, int lane,
                                           const float4* __restrict__ kT4, float* w) {
#pragma unroll
    for (int q = 0; q < 8; q++) w[q] = 0.0f;
    while (lo) {
        int j = __ffs(lo) - 1; lo &= lo - 1;
        int d = (j - lane) & 63;
        float4 p = kT4[d];
        float4 q = kT4[d ^ 32];
        w[0] += p.x; w[2] += p.y; w[4] += p.z; w[6] += p.w;
        w[1] += q.x; w[3] += q.y; w[5] += q.z; w[7] += q.w;
    }
    while (hi) {
        int j = __ffs(hi) + 31; hi &= hi - 1;
        int d = (j - lane) & 63;
        float4 p = kT4[d];
        float4 q = kT4[d ^ 32];
        w[0] += p.x; w[2] += p.y; w[4] += p.z; w[6] += p.w;
        w[1] += q.x; w[3] += q.y; w[5] += q.z; w[7] += q.w;
    }
}

__device__ __forceinline__ float softplus_sum(const float* w, const float* cc) {
    float s = 0.0f;
#pragma unroll
    for (int a = 0; a < ALPHA; a++) {
#pragma unroll
        for (int hh = 0; hh < 2; hh++) {
            float z = w[a * 2 + hh] + cc[a];
            s += fmaxf(z, 0.0f) + log1pf(__expf(-fabsf(z)));
        }
    }
    return s;
}

// ---------------- main kernel: one warp per batch sample, 32 samples/block ----------------

__global__ void __launch_bounds__(TPB, 1)
rbm_kernel(const float* __restrict__ v_data, const float* __restrict__ kern,
           const float* __restrict__ bsc, const float* __restrict__ cvec,
           GibbsKeys keys) {
    extern __shared__ unsigned char smem_raw[];
    float2* Tt  = (float2*)smem_raw;                  // [256][64] pair (i, i+32)
    float4* kT4 = (float4*)(smem_raw + KT4_OFF);      // [64]
    float*  W   = (float*)(smem_raw + W_OFF);         // [16][64]
    double* wsum = (double*)(smem_raw + WSUM_OFF);    // [WPB]

    const int tid = threadIdx.x;

    // ---- build W[s][d] = sum_a bit_a(s) * k[a][d]  (16x64) and kT4 ----
    {
        int idx = tid;
        if (idx < 16 * 64) {
            int s = idx >> 6, d = idx & 63;
            float acc = 0.0f;
#pragma unroll
            for (int a = 0; a < ALPHA; a++)
                if ((s >> a) & 1) acc += kern[a * NV + d];
            W[idx] = acc;
        }
        if (tid < 64)
            kT4[tid] = make_float4(kern[tid], kern[NV + tid], kern[2 * NV + tid], kern[3 * NV + tid]);
    }
    __syncthreads();

    // ---- build T[idx8][e]: idx8 = interleaved 2-bit fields t_a = bits (m, m+1) of H[a] ----
    // T.x = W[slo][e] + W[shi][(e-1)&63]; T.y = same with ^32 (output row i+32)
    for (int idx = tid; idx < 256 * 64; idx += TPB) {
        int i8 = idx >> 6, e = idx & 63;
        int slo = (i8 & 1) | ((i8 >> 1) & 2) | ((i8 >> 2) & 4) | ((i8 >> 3) & 8);
        int shi = ((i8 >> 1) & 1) | ((i8 >> 2) & 2) | ((i8 >> 3) & 4) | ((i8 >> 4) & 8);
        int em1 = (e - 1) & 63;
        float x = W[slo * 64 + e] + W[shi * 64 + em1];
        float y = W[slo * 64 + (e ^ 32)] + W[shi * 64 + (em1 ^ 32)];
        Tt[idx] = make_float2(x, y);
    }
    __syncthreads();

    const int lane = tid & 31;
    const int wid  = tid >> 5;
    const int b    = blockIdx.x * WPB + wid;

    const float bS = __ldg(bsc);
    float cc[ALPHA];
#pragma unroll
    for (int a = 0; a < ALPHA; a++) cc[a] = __ldg(cvec + a);

    // pack visible data into warp-uniform masks
    const float va = v_data[b * NV + lane];
    const float vb = v_data[b * NV + 32 + lane];
    uint32_t vlo = __ballot_sync(0xffffffffu, va > 0.5f);
    uint32_t vhi = __ballot_sync(0xffffffffu, vb > 0.5f);
    const uint32_t dlo = vlo, dhi = vhi;

    float w[8];

    compute_wv(dlo, dhi, lane, kT4, w);
    const float sp_d = softplus_sum(w, cc);

    const uint32_t bb = (uint32_t)b * (ALPHA * NV) + (uint32_t)lane;  // hidden ctr base
    const uint32_t mv = (uint32_t)b * NV + (uint32_t)lane;            // visible ctr base
    const int ebase = lane - 1;

#pragma unroll 1
    for (int t = 0; t < KSTEPS; t++) {
        compute_wv(vlo, vhi, lane, kT4, w);

        const uint32_t kh0 = keys.kh0[t], kh1 = keys.kh1[t];
        uint32_t hlo[ALPHA], hhi[ALPHA];
#pragma unroll
        for (int a = 0; a < ALPHA; a++) {
            const uint32_t mb = bb + (uint32_t)(a * NV);
            float p0 = sigmoidf(w[a * 2 + 0] + cc[a]);
            float p1 = sigmoidf(w[a * 2 + 1] + cc[a]);
            int h0 = u01(tf_bits(kh0, kh1, mb))       < p0;
            int h1 = u01(tf_bits(kh0, kh1, mb + 32u)) < p1;
            hlo[a] = __ballot_sync(0xffffffffu, h0);
            hhi[a] = __ballot_sync(0xffffffffu, h1);
        }

        // wh via pair-signature table: 32 dense iterations over m-pairs
        float wh0 = 0.0f, wh1 = 0.0f;
#pragma unroll
        for (int mm = 0; mm < 16; mm++) {
            const int m = mm * 2;
            uint32_t t0 = __funnelshift_r(hlo[0], hhi[0], m);
            uint32_t t1 = __funnelshift_r(hlo[1], hhi[1], m);
            uint32_t t2 = __funnelshift_r(hlo[2], hhi[2], m);
            uint32_t t3 = __funnelshift_r(hlo[3], hhi[3], m);
            uint32_t idx = (t0 & 3u) | ((t1 & 3u) << 2) | ((t2 & 3u) << 4) | ((t3 & 3u) << 6);
            int e = (ebase - m) & 63;
            float2 pr = Tt[idx * 64u + (uint32_t)e];
            wh0 += pr.x; wh1 += pr.y;
        }
#pragma unroll
        for (int mm = 0; mm < 16; mm++) {
            const int m = mm * 2;  // bits 32+m, 33+m
            uint32_t t0 = hhi[0] >> m;
            uint32_t t1 = hhi[1] >> m;
            uint32_t t2 = hhi[2] >> m;
            uint32_t t3 = hhi[3] >> m;
            uint32_t idx = (t0 & 3u) | ((t1 & 3u) << 2) | ((t2 & 3u) << 4) | ((t3 & 3u) << 6);
            int e = (ebase - 32 - m) & 63;
            float2 pr = Tt[idx * 64u + (uint32_t)e];
            wh0 += pr.x; wh1 += pr.y;
        }

        const uint32_t kv0 = keys.kv0[t], kv1 = keys.kv1[t];
        float q0 = sigmoidf(wh0 + bS);
        float q1 = sigmoidf(wh1 + bS);
        int n0 = u01(tf_bits(kv0, kv1, mv))       < q0;
        int n1 = u01(tf_bits(kv0, kv1, mv + 32u)) < q1;
        vlo = __ballot_sync(0xffffffffu, n0);
        vhi = __ballot_sync(0xffffffffu, n1);
    }

    compute_wv(vlo, vhi, lane, kT4, w);
    const float sp_m = softplus_sum(w, cc);

    // fe_data - fe_model = bS*(S_m - S_d) + (SP_m - SP_d)
    float x = sp_m - sp_d;
#pragma unroll
    for (int off = 16; off; off >>= 1) x += __shfl_xor_sync(0xffffffffu, x, off);

    if (lane == 0) {
        x += bS * (float)((__popc(vlo) + __popc(vhi)) - (__popc(dlo) + __popc(dhi)));
        wsum[wid] = (double)x;
    }
    __syncthreads();
    if (tid == 0) {
        double s = 0.0;
#pragma unroll
        for (int i = 0; i < WPB; i++) s += wsum[i];
        g_partials[blockIdx.x] = s;
    }
}

// ---------------- deterministic final reduction ----------------

__global__ void __launch_bounds__(256)
reduce_kernel(float* __restrict__ out) {
    __shared__ double sh[256];
    const int tid = threadIdx.x;
    double s = 0.0;
    for (int i = tid; i < NBLK; i += 256) s += g_partials[i];  // fixed order
    sh[tid] = s;
    __syncthreads();
    for (int off = 128; off; off >>= 1) {
        if (tid < off) sh[tid] += sh[tid + off];
        __syncthreads();
    }
    if (tid == 0) out[0] = (float)(sh[0] / (double)BATCH);
}

// ---------------- launch ----------------

extern "C" void kernel_launch(void* const* d_in, const int* in_sizes, int n_in,
                              void* d_out, int out_size) {
    (void)in_sizes; (void)n_in; (void)out_size;
    const float* v_data = (const float*)d_in[0];
    const float* kern   = (const float*)d_in[1];
    const float* bsc    = (const float*)d_in[2];
    const float* cvec   = (const float*)d_in[3];

    // JAX key schedule: key(42)=(0,42); fold-like split: keys[i]=threefry(k,(0,i))
    GibbsKeys keys;
    uint32_t k0 = 0u, k1 = 42u;
    for (int t = 0; t < KSTEPS; t++) {
        uint32_t n0, n1, h0, h1, w0, w1;
        tf2x32_host(k0, k1, 0u, 0u, &n0, &n1);
        tf2x32_host(k0, k1, 0u, 1u, &h0, &h1);
        tf2x32_host(k0, k1, 0u, 2u, &w0, &w1);
        keys.kh0[t] = h0; keys.kh1[t] = h1;
        keys.kv0[t] = w0; keys.kv1[t] = w1;
        k0 = n0; k1 = n1;
    }

    cudaFuncSetAttribute(rbm_kernel, cudaFuncAttributeMaxDynamicSharedMemorySize, SMEM_BYTES);
    rbm_kernel<<<NBLK, TPB, SMEM_BYTES>>>(v_data, kern, bsc, cvec, keys);
    reduce_kernel<<<1, 256>>>((float*)d_out);
}

// round 6
// speedup vs baseline: 2.6366x; 1.1202x over previous
#include <cuda_runtime.h>
#include <stdint.h>

// SymmetricRBM: B=65536 independent Gibbs chains, N=64 visible, ALPHA=4 hidden groups,
// circulant weights from kernel[4][64]. One warp per sample; binary states as u32-pair masks.
//
// Launch-constant tables in shared memory:
//   Tt [256][64] float2 : wh pair-signature table (8-bit sig over 4 channels x 2 bits)
//   Twv[16][64]  float4 : wv nibble-signature table (4 bits of V -> per-alpha sums)
// Both collapse data-dependent sparse bit loops into short dense LDS loops.

#define NV      64
#define ALPHA   4
#define BATCH   65536
#define KSTEPS  10
#define TPB     1024
#define WPB     32             // warps (=samples) per block
#define NBLK    (BATCH / WPB)  // 2048 blocks

// dynamic smem layout
#define T_BYTES    (256 * 64 * 8)            // float2 Tt[256][64]  = 131072
#define KT4_OFF    T_BYTES
#define KT4_BYTES  (64 * 16)                 // float4 kT4[64]      = 1024
#define W_OFF      (KT4_OFF + KT4_BYTES)
#define W_BYTES    (16 * 64 * 4)             // float  W[16][64]    = 4096
#define TWV_OFF    (W_OFF + W_BYTES)
#define TWV_BYTES  (16 * 64 * 16)            // float4 Twv[16][64]  = 16384
#define WSUM_OFF   (TWV_OFF + TWV_BYTES)
#define WSUM_BYTES (WPB * 8)
#define SMEM_BYTES (WSUM_OFF + WSUM_BYTES)   // 152832

struct GibbsKeys {
    uint32_t kh0[KSTEPS], kh1[KSTEPS];
    uint32_t kv0[KSTEPS], kv1[KSTEPS];
};

__device__ double g_partials[NBLK];

// ---------------- Threefry-2x32 (20 rounds), JAX-compatible ----------------

__host__ static uint32_t rotl32h(uint32_t x, int r) {
    return (x << r) | (x >> (32 - r));
}

__host__ static void tf2x32_host(uint32_t k0, uint32_t k1, uint32_t c0, uint32_t c1,
                                 uint32_t* o0, uint32_t* o1) {
    uint32_t ks2 = k0 ^ k1 ^ 0x1BD11BDAu;
    uint32_t x0 = c0 + k0, x1 = c1 + k1;
#define HR4A x0+=x1; x1=rotl32h(x1,13); x1^=x0; x0+=x1; x1=rotl32h(x1,15); x1^=x0; \
             x0+=x1; x1=rotl32h(x1,26); x1^=x0; x0+=x1; x1=rotl32h(x1, 6); x1^=x0;
#define HR4B x0+=x1; x1=rotl32h(x1,17); x1^=x0; x0+=x1; x1=rotl32h(x1,29); x1^=x0; \
             x0+=x1; x1=rotl32h(x1,16); x1^=x0; x0+=x1; x1=rotl32h(x1,24); x1^=x0;
    HR4A; x0 += k1;  x1 += ks2 + 1u;
    HR4B; x0 += ks2; x1 += k0  + 2u;
    HR4A; x0 += k0;  x1 += k1  + 3u;
    HR4B; x0 += k1;  x1 += ks2 + 4u;
    HR4A; x0 += ks2; x1 += k0  + 5u;
    *o0 = x0; *o1 = x1;
}
#undef HR4A
#undef HR4B

// device rotate: single SHF via funnel shift
__device__ __forceinline__ uint32_t rotl32d(uint32_t x, int r) {
    return __funnelshift_l(x, x, r);
}

// counter hi word always 0; JAX partitionable random_bits -> x0 ^ x1
__device__ __forceinline__ uint32_t tf_bits(uint32_t k0, uint32_t k1, uint32_t ctr_lo) {
    uint32_t ks2 = k0 ^ k1 ^ 0x1BD11BDAu;
    uint32_t x0 = k0;
    uint32_t x1 = ctr_lo + k1;
#define R4A  x0+=x1; x1=rotl32d(x1,13); x1^=x0; x0+=x1; x1=rotl32d(x1,15); x1^=x0; \
             x0+=x1; x1=rotl32d(x1,26); x1^=x0; x0+=x1; x1=rotl32d(x1, 6); x1^=x0;
#define R4B  x0+=x1; x1=rotl32d(x1,17); x1^=x0; x0+=x1; x1=rotl32d(x1,29); x1^=x0; \
             x0+=x1; x1=rotl32d(x1,16); x1^=x0; x0+=x1; x1=rotl32d(x1,24); x1^=x0;
    R4A; x0 += k1;  x1 += ks2 + 1u;
    R4B; x0 += ks2; x1 += k0  + 2u;
    R4A; x0 += k0;  x1 += k1  + 3u;
    R4B; x0 += k1;  x1 += ks2 + 4u;
    R4A; x0 += ks2; x1 += k0  + 5u;
    return x0 ^ x1;
#undef R4A
#undef R4B
}

__device__ __forceinline__ float u01(uint32_t bits) {
    return __uint_as_float((bits >> 9) | 0x3f800000u) - 1.0f;
}

__device__ __forceinline__ float sigmoidf(float z) {
    return __fdividef(1.0f, 1.0f + __expf(-z));
}

// ---------------- wv: circulant forward via nibble table, 16 dense iterations ----------------
// wv[a,lane] -> w[2a], wv[a,lane+32] -> w[2a+1]
__device__ __forceinline__ void compute_wv(uint32_t lo, uint32_t hi, int lane,
                                           const float4* __restrict__ Twv, float* w) {
#pragma unroll
    for (int q = 0; q < 8; q++) w[q] = 0.0f;
    int d = (-lane) & 63;   // (j0 - lane) & 63 at j0 = 0; advances by 4 per nibble
#pragma unroll
    for (int n = 0; n < 16; n++) {
        uint32_t s = (n < 8) ? ((lo >> (n * 4)) & 15u)
                             : ((hi >> ((n - 8) * 4)) & 15u);
        const float4* row = Twv + s * 64;
        float4 x = row[d];
        float4 y = row[d ^ 32];
        w[0] += x.x; w[2] += x.y; w[4] += x.z; w[6] += x.w;
        w[1] += y.x; w[3] += y.y; w[5] += y.z; w[7] += y.w;
        d = (d + 4) & 63;
    }
}

__device__ __forceinline__ float softplus_sum(const float* w, const float* cc) {
    float s = 0.0f;
#pragma unroll
    for (int a = 0; a < ALPHA; a++) {
#pragma unroll
        for (int hh = 0; hh < 2; hh++) {
            float z = w[a * 2 + hh] + cc[a];
            s += fmaxf(z, 0.0f) + log1pf(__expf(-fabsf(z)));
        }
    }
    return s;
}

// ---------------- main kernel: one warp per batch sample, 32 samples/block ----------------

__global__ void __launch_bounds__(TPB, 1)
rbm_kernel(const float* __restrict__ v_data, const float* __restrict__ kern,
           const float* __restrict__ bsc, const float* __restrict__ cvec,
           GibbsKeys keys) {
    extern __shared__ unsigned char smem_raw[];
    float2* Tt   = (float2*)smem_raw;                  // [256][64] pair (i, i+32)
    float4* kT4  = (float4*)(smem_raw + KT4_OFF);      // [64]
    float*  W    = (float*)(smem_raw + W_OFF);         // [16][64]
    float4* Twv  = (float4*)(smem_raw + TWV_OFF);      // [16][64]
    double* wsum = (double*)(smem_raw + WSUM_OFF);     // [WPB]

    const int tid = threadIdx.x;

    // ---- phase 1: W[s][d] = sum_a bit_a(s)*k[a][d]  and  kT4[d] = (k0..k3)[d] ----
    {
        if (tid < 16 * 64) {
            int s = tid >> 6, d = tid & 63;
            float acc = 0.0f;
#pragma unroll
            for (int a = 0; a < ALPHA; a++)
                if ((s >> a) & 1) acc += kern[a * NV + d];
            W[tid] = acc;
        }
        if (tid < 64)
            kT4[tid] = make_float4(kern[tid], kern[NV + tid], kern[2 * NV + tid], kern[3 * NV + tid]);
    }
    __syncthreads();

    // ---- phase 2a: Tt[idx8][e] (wh pair table) ----
    // idx8 = interleaved 2-bit fields (bits m, m+1 of each H[a])
    // Tt.x = W[slo][e] + W[shi][(e-1)&63]; Tt.y = same with ^32
    for (int idx = tid; idx < 256 * 64; idx += TPB) {
        int i8 = idx >> 6, e = idx & 63;
        int slo = (i8 & 1) | ((i8 >> 1) & 2) | ((i8 >> 2) & 4) | ((i8 >> 3) & 8);
        int shi = ((i8 >> 1) & 1) | ((i8 >> 2) & 2) | ((i8 >> 3) & 4) | ((i8 >> 4) & 8);
        int em1 = (e - 1) & 63;
        float x = W[slo * 64 + e] + W[shi * 64 + em1];
        float y = W[slo * 64 + (e ^ 32)] + W[shi * 64 + (em1 ^ 32)];
        Tt[idx] = make_float2(x, y);
    }

    // ---- phase 2b: Twv[s][d] = sum_{r in bits(s)} kT4[(d+r)&63]  (wv nibble table) ----
    if (tid < 16 * 64) {
        int s = tid >> 6, d = tid & 63;
        float4 acc = make_float4(0.f, 0.f, 0.f, 0.f);
#pragma unroll
        for (int r = 0; r < 4; r++) {
            if ((s >> r) & 1) {
                float4 k = kT4[(d + r) & 63];
                acc.x += k.x; acc.y += k.y; acc.z += k.z; acc.w += k.w;
            }
        }
        Twv[tid] = acc;
    }
    __syncthreads();

    const int lane = tid & 31;
    const int wid  = tid >> 5;
    const int b    = blockIdx.x * WPB + wid;

    const float bS = __ldg(bsc);
    float cc[ALPHA];
#pragma unroll
    for (int a = 0; a < ALPHA; a++) cc[a] = __ldg(cvec + a);

    // pack visible data into warp-uniform masks
    const float va = v_data[b * NV + lane];
    const float vb = v_data[b * NV + 32 + lane];
    uint32_t vlo = __ballot_sync(0xffffffffu, va > 0.5f);
    uint32_t vhi = __ballot_sync(0xffffffffu, vb > 0.5f);
    const uint32_t dlo = vlo, dhi = vhi;

    float w[8];

    compute_wv(dlo, dhi, lane, Twv, w);
    const float sp_d = softplus_sum(w, cc);

    const uint32_t bb = (uint32_t)b * (ALPHA * NV) + (uint32_t)lane;  // hidden ctr base
    const uint32_t mv = (uint32_t)b * NV + (uint32_t)lane;            // visible ctr base
    const int ebase = lane - 1;

#pragma unroll 1
    for (int t = 0; t < KSTEPS; t++) {
        compute_wv(vlo, vhi, lane, Twv, w);

        const uint32_t kh0 = keys.kh0[t], kh1 = keys.kh1[t];
        uint32_t hlo[ALPHA], hhi[ALPHA];
#pragma unroll
        for (int a = 0; a < ALPHA; a++) {
            const uint32_t mb = bb + (uint32_t)(a * NV);
            float p0 = sigmoidf(w[a * 2 + 0] + cc[a]);
            float p1 = sigmoidf(w[a * 2 + 1] + cc[a]);
            int h0 = u01(tf_bits(kh0, kh1, mb))       < p0;
            int h1 = u01(tf_bits(kh0, kh1, mb + 32u)) < p1;
            hlo[a] = __ballot_sync(0xffffffffu, h0);
            hhi[a] = __ballot_sync(0xffffffffu, h1);
        }

        // wh via pair-signature table: 32 dense iterations over m-pairs
        float wh0 = 0.0f, wh1 = 0.0f;
#pragma unroll
        for (int mm = 0; mm < 16; mm++) {
            const int m = mm * 2;
            uint32_t t0 = __funnelshift_r(hlo[0], hhi[0], m);
            uint32_t t1 = __funnelshift_r(hlo[1], hhi[1], m);
            uint32_t t2 = __funnelshift_r(hlo[2], hhi[2], m);
            uint32_t t3 = __funnelshift_r(hlo[3], hhi[3], m);
            uint32_t idx = (t0 & 3u) | ((t1 & 3u) << 2) | ((t2 & 3u) << 4) | ((t3 & 3u) << 6);
            int e = (ebase - m) & 63;
            float2 pr = Tt[idx * 64u + (uint32_t)e];
            wh0 += pr.x; wh1 += pr.y;
        }
#pragma unroll
        for (int mm = 0; mm < 16; mm++) {
            const int m = mm * 2;  // bits 32+m, 33+m
            uint32_t t0 = hhi[0] >> m;
            uint32_t t1 = hhi[1] >> m;
            uint32_t t2 = hhi[2] >> m;
            uint32_t t3 = hhi[3] >> m;
            uint32_t idx = (t0 & 3u) | ((t1 & 3u) << 2) | ((t2 & 3u) << 4) | ((t3 & 3u) << 6);
            int e = (ebase - 32 - m) & 63;
            float2 pr = Tt[idx * 64u + (uint32_t)e];
            wh0 += pr.x; wh1 += pr.y;
        }

        const uint32_t kv0 = keys.kv0[t], kv1 = keys.kv1[t];
        float q0 = sigmoidf(wh0 + bS);
        float q1 = sigmoidf(wh1 + bS);
        int n0 = u01(tf_bits(kv0, kv1, mv))       < q0;
        int n1 = u01(tf_bits(kv0, kv1, mv + 32u)) < q1;
        vlo = __ballot_sync(0xffffffffu, n0);
        vhi = __ballot_sync(0xffffffffu, n1);
    }

    compute_wv(vlo, vhi, lane, Twv, w);
    const float sp_m = softplus_sum(w, cc);

    // fe_data - fe_model = bS*(S_m - S_d) + (SP_m - SP_d)
    float x = sp_m - sp_d;
#pragma unroll
    for (int off = 16; off; off >>= 1) x += __shfl_xor_sync(0xffffffffu, x, off);

    if (lane == 0) {
        x += bS * (float)((__popc(vlo) + __popc(vhi)) - (__popc(dlo) + __popc(dhi)));
        wsum[wid] = (double)x;
    }
    __syncthreads();
    if (tid == 0) {
        double s = 0.0;
#pragma unroll
        for (int i = 0; i < WPB; i++) s += wsum[i];
        g_partials[blockIdx.x] = s;
    }
}

// ---------------- deterministic final reduction ----------------

__global__ void __launch_bounds__(256)
reduce_kernel(float* __restrict__ out) {
    __shared__ double sh[256];
    const int tid = threadIdx.x;
    double s = 0.0;
    for (int i = tid; i < NBLK; i += 256) s += g_partials[i];  // fixed order
    sh[tid] = s;
    __syncthreads();
    for (int off = 128; off; off >>= 1) {
        if (tid < off) sh[tid] += sh[tid + off];
        __syncthreads();
    }
    if (tid == 0) out[0] = (float)(sh[0] / (double)BATCH);
}

// ---------------- launch ----------------

extern "C" void kernel_launch(void* const* d_in, const int* in_sizes, int n_in,
                              void* d_out, int out_size) {
    (void)in_sizes; (void)n_in; (void)out_size;
    const float* v_data = (const float*)d_in[0];
    const float* kern   = (const float*)d_in[1];
    const float* bsc    = (const float*)d_in[2];
    const float* cvec   = (const float*)d_in[3];

    // JAX key schedule: key(42)=(0,42); fold-like split: keys[i]=threefry(k,(0,i))
    GibbsKeys keys;
    uint32_t k0 = 0u, k1 = 42u;
    for (int t = 0; t < KSTEPS; t++) {
        uint32_t n0, n1, h0, h1, w0, w1;
        tf2x32_host(k0, k1, 0u, 0u, &n0, &n1);
        tf2x32_host(k0, k1, 0u, 1u, &h0, &h1);
        tf2x32_host(k0, k1, 0u, 2u, &w0, &w1);
        keys.kh0[t] = h0; keys.kh1[t] = h1;
        keys.kv0[t] = w0; keys.kv1[t] = w1;
        k0 = n0; k1 = n1;
    }

    cudaFuncSetAttribute(rbm_kernel, cudaFuncAttributeMaxDynamicSharedMemorySize, SMEM_BYTES);
    rbm_kernel<<<NBLK, TPB, SMEM_BYTES>>>(v_data, kern, bsc, cvec, keys);
    reduce_kernel<<<1, 256>>>((float*)d_out);
}

// round 7
// speedup vs baseline: 3.0132x; 1.1428x over previous
#include <cuda_runtime.h>
#include <stdint.h>

// SymmetricRBM: B=65536 independent Gibbs chains, N=64 visible, ALPHA=4 hidden groups,
// circulant weights from kernel[4][64]. One warp per sample; binary states as u32-pair masks.
//
// Launch-constant tables in shared memory:
//   Tt [256][64] float2 : wh pair-signature table (8-bit sig over 4 channels x 2 bits)
//   Twv[16][64]  float4 : wv nibble-signature table (4 bits of V -> per-alpha sums)
// Accumulation uses packed add.rn.f32x2 (bit-identical per-lane scalar chains).

#define NV      64
#define ALPHA   4
#define BATCH   65536
#define KSTEPS  10
#define TPB     1024
#define WPB     32             // warps (=samples) per block
#define NBLK    (BATCH / WPB)  // 2048 blocks

// dynamic smem layout
#define T_BYTES    (256 * 64 * 8)            // float2 Tt[256][64]  = 131072
#define KT4_OFF    T_BYTES
#define KT4_BYTES  (64 * 16)                 // float4 kT4[64]      = 1024
#define W_OFF      (KT4_OFF + KT4_BYTES)
#define W_BYTES    (16 * 64 * 4)             // float  W[16][64]    = 4096
#define TWV_OFF    (W_OFF + W_BYTES)
#define TWV_BYTES  (16 * 64 * 16)            // float4 Twv[16][64]  = 16384
#define WSUM_OFF   (TWV_OFF + TWV_BYTES)
#define WSUM_BYTES (WPB * 8)
#define SMEM_BYTES (WSUM_OFF + WSUM_BYTES)   // 152832

struct GibbsKeys {
    uint32_t kh0[KSTEPS], kh1[KSTEPS];
    uint32_t kv0[KSTEPS], kv1[KSTEPS];
};

__device__ double g_partials[NBLK];

// ---------------- packed f32x2 helpers ----------------

__device__ __forceinline__ void addf32x2(uint64_t& acc, uint64_t v) {
    asm("add.rn.f32x2 %0, %0, %1;" : "+l"(acc) : "l"(v));
}
__device__ __forceinline__ void unpack2(float& lo, float& hi, uint64_t v) {
    uint32_t a, b;
    asm("mov.b64 {%0, %1}, %2;" : "=r"(a), "=r"(b) : "l"(v));
    lo = __uint_as_float(a); hi = __uint_as_float(b);
}

// ---------------- Threefry-2x32 (20 rounds), JAX-compatible ----------------

__host__ static uint32_t rotl32h(uint32_t x, int r) {
    return (x << r) | (x >> (32 - r));
}

__host__ static void tf2x32_host(uint32_t k0, uint32_t k1, uint32_t c0, uint32_t c1,
                                 uint32_t* o0, uint32_t* o1) {
    uint32_t ks2 = k0 ^ k1 ^ 0x1BD11BDAu;
    uint32_t x0 = c0 + k0, x1 = c1 + k1;
#define HR4A x0+=x1; x1=rotl32h(x1,13); x1^=x0; x0+=x1; x1=rotl32h(x1,15); x1^=x0; \
             x0+=x1; x1=rotl32h(x1,26); x1^=x0; x0+=x1; x1=rotl32h(x1, 6); x1^=x0;
#define HR4B x0+=x1; x1=rotl32h(x1,17); x1^=x0; x0+=x1; x1=rotl32h(x1,29); x1^=x0; \
             x0+=x1; x1=rotl32h(x1,16); x1^=x0; x0+=x1; x1=rotl32h(x1,24); x1^=x0;
    HR4A; x0 += k1;  x1 += ks2 + 1u;
    HR4B; x0 += ks2; x1 += k0  + 2u;
    HR4A; x0 += k0;  x1 += k1  + 3u;
    HR4B; x0 += k1;  x1 += ks2 + 4u;
    HR4A; x0 += ks2; x1 += k0  + 5u;
    *o0 = x0; *o1 = x1;
}
#undef HR4A
#undef HR4B

__device__ __forceinline__ uint32_t rotl32d(uint32_t x, int r) {
    return __funnelshift_l(x, x, r);
}

// counter hi word always 0; JAX partitionable random_bits -> x0 ^ x1
__device__ __forceinline__ uint32_t tf_bits(uint32_t k0, uint32_t k1, uint32_t ctr_lo) {
    uint32_t ks2 = k0 ^ k1 ^ 0x1BD11BDAu;
    uint32_t x0 = k0;
    uint32_t x1 = ctr_lo + k1;
#define R4A  x0+=x1; x1=rotl32d(x1,13); x1^=x0; x0+=x1; x1=rotl32d(x1,15); x1^=x0; \
             x0+=x1; x1=rotl32d(x1,26); x1^=x0; x0+=x1; x1=rotl32d(x1, 6); x1^=x0;
#define R4B  x0+=x1; x1=rotl32d(x1,17); x1^=x0; x0+=x1; x1=rotl32d(x1,29); x1^=x0; \
             x0+=x1; x1=rotl32d(x1,16); x1^=x0; x0+=x1; x1=rotl32d(x1,24); x1^=x0;
    R4A; x0 += k1;  x1 += ks2 + 1u;
    R4B; x0 += ks2; x1 += k0  + 2u;
    R4A; x0 += k0;  x1 += k1  + 3u;
    R4B; x0 += k1;  x1 += ks2 + 4u;
    R4A; x0 += ks2; x1 += k0  + 5u;
    return x0 ^ x1;
#undef R4A
#undef R4B
}

__device__ __forceinline__ float u01(uint32_t bits) {
    return __uint_as_float((bits >> 9) | 0x3f800000u) - 1.0f;
}

// ---------------- wv: circulant forward via nibble table, packed accumulation ----------------
// Packed accumulators: P0=(w0,w2) P1=(w4,w6) from row[d]; P2=(w1,w3) P3=(w5,w7) from row[d^32]
struct WvAcc { uint64_t P0, P1, P2, P3; };

__device__ __forceinline__ WvAcc compute_wv(uint32_t lo, uint32_t hi, int lane,
                                            const unsigned char* __restrict__ TwvRaw) {
    WvAcc A; A.P0 = A.P1 = A.P2 = A.P3 = 0ull;   // (0.0f, 0.0f)
    int d16 = (((-lane) & 63) << 4);             // byte offset of float4 row entry
#pragma unroll
    for (int n = 0; n < 16; n++) {
        uint32_t s = ((n < 8) ? (lo >> (n * 4)) : (hi >> ((n - 8) * 4))) & 15u;
        const unsigned char* row = TwvRaw + s * 1024u;
        ulonglong2 x = *(const ulonglong2*)(row + d16);
        ulonglong2 y = *(const ulonglong2*)(row + (d16 ^ 512));
        addf32x2(A.P0, x.x); addf32x2(A.P1, x.y);
        addf32x2(A.P2, y.x); addf32x2(A.P3, y.y);
        d16 = (d16 + 64) & 1023;
    }
    return A;
}

// unpack to w[8]: w[2a]=wv[a,lane], w[2a+1]=wv[a,lane+32]
__device__ __forceinline__ void unpack_wv(const WvAcc& A, float* w) {
    unpack2(w[0], w[2], A.P0);
    unpack2(w[4], w[6], A.P1);
    unpack2(w[1], w[3], A.P2);
    unpack2(w[5], w[7], A.P3);
}

__device__ __forceinline__ float softplus_sum(const float* w, const float* cc) {
    float s = 0.0f;
#pragma unroll
    for (int a = 0; a < ALPHA; a++) {
#pragma unroll
        for (int hh = 0; hh < 2; hh++) {
            float z = w[a * 2 + hh] + cc[a];
            s += fmaxf(z, 0.0f) + log1pf(__expf(-fabsf(z)));
        }
    }
    return s;
}

// Bernoulli(sigmoid(z)) draw without divide: u < 1/(1+e^-z) <=> u*e^-z + u < 1
__device__ __forceinline__ int bern_sig(float u, float z) {
    float e = __expf(-z);
    return fmaf(u, e, u) < 1.0f;
}

// ---------------- main kernel: one warp per batch sample, 32 samples/block ----------------

__global__ void __launch_bounds__(TPB, 1)
rbm_kernel(const float* __restrict__ v_data, const float* __restrict__ kern,
           const float* __restrict__ bsc, const float* __restrict__ cvec,
           GibbsKeys keys) {
    extern __shared__ unsigned char smem_raw[];
    float2* Tt   = (float2*)smem_raw;                  // [256][64] pair (i, i+32)
    float4* kT4  = (float4*)(smem_raw + KT4_OFF);      // [64]
    float*  W    = (float*)(smem_raw + W_OFF);         // [16][64]
    float4* Twv  = (float4*)(smem_raw + TWV_OFF);      // [16][64]
    double* wsum = (double*)(smem_raw + WSUM_OFF);     // [WPB]
    const unsigned char* TwvRaw = smem_raw + TWV_OFF;

    const int tid = threadIdx.x;

    // ---- phase 1: W[s][d] = sum_a bit_a(s)*k[a][d]  and  kT4[d] = (k0..k3)[d] ----
    {
        if (tid < 16 * 64) {
            int s = tid >> 6, d = tid & 63;
            float acc = 0.0f;
#pragma unroll
            for (int a = 0; a < ALPHA; a++)
                if ((s >> a) & 1) acc += kern[a * NV + d];
            W[tid] = acc;
        }
        if (tid < 64)
            kT4[tid] = make_float4(kern[tid], kern[NV + tid], kern[2 * NV + tid], kern[3 * NV + tid]);
    }
    __syncthreads();

    // ---- phase 2a: Tt[idx8][e] (wh pair table) ----
    // idx8 = interleaved 2-bit fields (bits m, m+1 of each H[a])
    // Tt.x = W[slo][e] + W[shi][(e-1)&63]; Tt.y = same with ^32
    for (int idx = tid; idx < 256 * 64; idx += TPB) {
        int i8 = idx >> 6, e = idx & 63;
        int slo = (i8 & 1) | ((i8 >> 1) & 2) | ((i8 >> 2) & 4) | ((i8 >> 3) & 8);
        int shi = ((i8 >> 1) & 1) | ((i8 >> 2) & 2) | ((i8 >> 3) & 4) | ((i8 >> 4) & 8);
        int em1 = (e - 1) & 63;
        float x = W[slo * 64 + e] + W[shi * 64 + em1];
        float y = W[slo * 64 + (e ^ 32)] + W[shi * 64 + (em1 ^ 32)];
        Tt[idx] = make_float2(x, y);
    }

    // ---- phase 2b: Twv[s][d] = sum_{r in bits(s)} kT4[(d+r)&63]  (wv nibble table) ----
    if (tid < 16 * 64) {
        int s = tid >> 6, d = tid & 63;
        float4 acc = make_float4(0.f, 0.f, 0.f, 0.f);
#pragma unroll
        for (int r = 0; r < 4; r++) {
            if ((s >> r) & 1) {
                float4 k = kT4[(d + r) & 63];
                acc.x += k.x; acc.y += k.y; acc.z += k.z; acc.w += k.w;
            }
        }
        Twv[tid] = acc;
    }
    __syncthreads();

    const int lane = tid & 31;
    const int wid  = tid >> 5;
    const int b    = blockIdx.x * WPB + wid;

    const float bS = __ldg(bsc);
    float cc[ALPHA];
#pragma unroll
    for (int a = 0; a < ALPHA; a++) cc[a] = __ldg(cvec + a);

    // pack visible data into warp-uniform masks
    const float va = v_data[b * NV + lane];
    const float vb = v_data[b * NV + 32 + lane];
    uint32_t vlo = __ballot_sync(0xffffffffu, va > 0.5f);
    uint32_t vhi = __ballot_sync(0xffffffffu, vb > 0.5f);
    const uint32_t dlo = vlo, dhi = vhi;

    float w[8];

    // wv(V_data): shared by sp_d and step 0's hidden sampling
    {
        WvAcc A = compute_wv(dlo, dhi, lane, TwvRaw);
        unpack_wv(A, w);
    }
    const float sp_d = softplus_sum(w, cc);

    const uint32_t bb = (uint32_t)b * (ALPHA * NV) + (uint32_t)lane;  // hidden ctr base
    const uint32_t mv = (uint32_t)b * NV + (uint32_t)lane;            // visible ctr base
    const int ebase = lane - 1;

#pragma unroll 1
    for (int t = 0; t < KSTEPS; t++) {
        // ---- sample hidden from current w (wv of current V) ----
        const uint32_t kh0 = keys.kh0[t], kh1 = keys.kh1[t];
        uint32_t hlo[ALPHA], hhi[ALPHA];
#pragma unroll
        for (int a = 0; a < ALPHA; a++) {
            const uint32_t mb = bb + (uint32_t)(a * NV);
            float u0 = u01(tf_bits(kh0, kh1, mb));
            float u1 = u01(tf_bits(kh0, kh1, mb + 32u));
            int h0 = bern_sig(u0, w[a * 2 + 0] + cc[a]);
            int h1 = bern_sig(u1, w[a * 2 + 1] + cc[a]);
            hlo[a] = __ballot_sync(0xffffffffu, h0);
            hhi[a] = __ballot_sync(0xffffffffu, h1);
        }

        // ---- wh via pair-signature table: 32 dense iterations, packed accumulate ----
        uint64_t WH = 0ull;  // (wh0, wh1)
#pragma unroll
        for (int mm = 0; mm < 16; mm++) {
            const int m = mm * 2;
            uint32_t t0 = __funnelshift_r(hlo[0], hhi[0], m);
            uint32_t t1 = __funnelshift_r(hlo[1], hhi[1], m);
            uint32_t t2 = __funnelshift_r(hlo[2], hhi[2], m);
            uint32_t t3 = __funnelshift_r(hlo[3], hhi[3], m);
            uint32_t idx = (t0 & 3u) | ((t1 & 3u) << 2) | ((t2 & 3u) << 4) | ((t3 & 3u) << 6);
            int e = (ebase - m) & 63;
            addf32x2(WH, *(const uint64_t*)(Tt + idx * 64u + (uint32_t)e));
        }
#pragma unroll
        for (int mm = 0; mm < 16; mm++) {
            const int m = mm * 2;  // bits 32+m, 33+m
            uint32_t t0 = hhi[0] >> m;
            uint32_t t1 = hhi[1] >> m;
            uint32_t t2 = hhi[2] >> m;
            uint32_t t3 = hhi[3] >> m;
            uint32_t idx = (t0 & 3u) | ((t1 & 3u) << 2) | ((t2 & 3u) << 4) | ((t3 & 3u) << 6);
            int e = (ebase - 32 - m) & 63;
            addf32x2(WH, *(const uint64_t*)(Tt + idx * 64u + (uint32_t)e));
        }
        float wh0, wh1;
        unpack2(wh0, wh1, WH);

        // ---- sample visible ----
        const uint32_t kv0 = keys.kv0[t], kv1 = keys.kv1[t];
        float u0 = u01(tf_bits(kv0, kv1, mv));
        float u1 = u01(tf_bits(kv0, kv1, mv + 32u));
        int n0 = bern_sig(u0, wh0 + bS);
        int n1 = bern_sig(u1, wh1 + bS);
        vlo = __ballot_sync(0xffffffffu, n0);
        vhi = __ballot_sync(0xffffffffu, n1);

        // ---- wv of new V (feeds next step's hidden sampling, or sp_m after t=9) ----
        WvAcc A = compute_wv(vlo, vhi, lane, TwvRaw);
        unpack_wv(A, w);
    }

    const float sp_m = softplus_sum(w, cc);

    // fe_data - fe_model = bS*(S_m - S_d) + (SP_m - SP_d)
    float x = sp_m - sp_d;
#pragma unroll
    for (int off = 16; off; off >>= 1) x += __shfl_xor_sync(0xffffffffu, x, off);

    if (lane == 0) {
        x += bS * (float)((__popc(vlo) + __popc(vhi)) - (__popc(dlo) + __popc(dhi)));
        wsum[wid] = (double)x;
    }
    __syncthreads();
    if (tid == 0) {
        double s = 0.0;
#pragma unroll
        for (int i = 0; i < WPB; i++) s += wsum[i];
        g_partials[blockIdx.x] = s;
    }
}

// ---------------- deterministic final reduction ----------------

__global__ void __launch_bounds__(256)
reduce_kernel(float* __restrict__ out) {
    __shared__ double sh[256];
    const int tid = threadIdx.x;
    double s = 0.0;
    for (int i = tid; i < NBLK; i += 256) s += g_partials[i];  // fixed order
    sh[tid] = s;
    __syncthreads();
    for (int off = 128; off; off >>= 1) {
        if (tid < off) sh[tid] += sh[tid + off];
        __syncthreads();
    }
    if (tid == 0) out[0] = (float)(sh[0] / (double)BATCH);
}

// ---------------- launch ----------------

extern "C" void kernel_launch(void* const* d_in, const int* in_sizes, int n_in,
                              void* d_out, int out_size) {
    (void)in_sizes; (void)n_in; (void)out_size;
    const float* v_data = (const float*)d_in[0];
    const float* kern   = (const float*)d_in[1];
    const float* bsc    = (const float*)d_in[2];
    const float* cvec   = (const float*)d_in[3];

    // JAX key schedule: key(42)=(0,42); fold-like split: keys[i]=threefry(k,(0,i))
    GibbsKeys keys;
    uint32_t k0 = 0u, k1 = 42u;
    for (int t = 0; t < KSTEPS; t++) {
        uint32_t n0, n1, h0, h1, w0, w1;
        tf2x32_host(k0, k1, 0u, 0u, &n0, &n1);
        tf2x32_host(k0, k1, 0u, 1u, &h0, &h1);
        tf2x32_host(k0, k1, 0u, 2u, &w0, &w1);
        keys.kh0[t] = h0; keys.kh1[t] = h1;
        keys.kv0[t] = w0; keys.kv1[t] = w1;
        k0 = n0; k1 = n1;
    }

    cudaFuncSetAttribute(rbm_kernel, cudaFuncAttributeMaxDynamicSharedMemorySize, SMEM_BYTES);
    rbm_kernel<<<NBLK, TPB, SMEM_BYTES>>>(v_data, kern, bsc, cvec, keys);
    reduce_kernel<<<1, 256>>>((float*)d_out);
}

// round 8
// speedup vs baseline: 3.4072x; 1.1308x over previous
#include <cuda_runtime.h>
#include <stdint.h>

// SymmetricRBM: B=65536 independent Gibbs chains, N=64 visible, ALPHA=4 hidden groups,
// circulant weights from kernel[4][64]. One warp per sample; binary states as u32-pair masks.
//
// Launch-constant tables in shared memory:
//   Tt [256][64] float2 : wh pair-signature table (8-bit sig over 4 channels x 2 bits)
//   Twv[16][64]  float4 : wv nibble-signature table (4 bits of V -> per-alpha sums)
// Warp-uniform signatures are built once per-lane and broadcast via SHFL in the
// table loops (each lane owns one loop-iteration's signature, pre-scaled to a byte
// row offset). Accumulation uses packed add.rn.f32x2; add order identical to the
// scalar formulation.

#define NV      64
#define ALPHA   4
#define BATCH   65536
#define KSTEPS  10
#define TPB     1024
#define WPB     32             // warps (=samples) per block
#define NBLK    (BATCH / WPB)  // 2048 blocks

// dynamic smem layout
#define T_BYTES    (256 * 64 * 8)            // float2 Tt[256][64]  = 131072
#define KT4_OFF    T_BYTES
#define KT4_BYTES  (64 * 16)                 // float4 kT4[64]      = 1024
#define W_OFF      (KT4_OFF + KT4_BYTES)
#define W_BYTES    (16 * 64 * 4)             // float  W[16][64]    = 4096
#define TWV_OFF    (W_OFF + W_BYTES)
#define TWV_BYTES  (16 * 64 * 16)            // float4 Twv[16][64]  = 16384
#define WSUM_OFF   (TWV_OFF + TWV_BYTES)
#define WSUM_BYTES (WPB * 8)
#define SMEM_BYTES (WSUM_OFF + WSUM_BYTES)   // 152832

struct GibbsKeys {
    uint32_t kh0[KSTEPS], kh1[KSTEPS];
    uint32_t kv0[KSTEPS], kv1[KSTEPS];
};

__device__ double g_partials[NBLK];

// ---------------- packed f32x2 helpers ----------------

__device__ __forceinline__ void addf32x2(uint64_t& acc, uint64_t v) {
    asm("add.rn.f32x2 %0, %0, %1;" : "+l"(acc) : "l"(v));
}
__device__ __forceinline__ void unpack2(float& lo, float& hi, uint64_t v) {
    uint32_t a, b;
    asm("mov.b64 {%0, %1}, %2;" : "=r"(a), "=r"(b) : "l"(v));
    lo = __uint_as_float(a); hi = __uint_as_float(b);
}

// ---------------- Threefry-2x32 (20 rounds), JAX-compatible ----------------

__host__ static uint32_t rotl32h(uint32_t x, int r) {
    return (x << r) | (x >> (32 - r));
}

__host__ static void tf2x32_host(uint32_t k0, uint32_t k1, uint32_t c0, uint32_t c1,
                                 uint32_t* o0, uint32_t* o1) {
    uint32_t ks2 = k0 ^ k1 ^ 0x1BD11BDAu;
    uint32_t x0 = c0 + k0, x1 = c1 + k1;
#define HR4A x0+=x1; x1=rotl32h(x1,13); x1^=x0; x0+=x1; x1=rotl32h(x1,15); x1^=x0; \
             x0+=x1; x1=rotl32h(x1,26); x1^=x0; x0+=x1; x1=rotl32h(x1, 6); x1^=x0;
#define HR4B x0+=x1; x1=rotl32h(x1,17); x1^=x0; x0+=x1; x1=rotl32h(x1,29); x1^=x0; \
             x0+=x1; x1=rotl32h(x1,16); x1^=x0; x0+=x1; x1=rotl32h(x1,24); x1^=x0;
    HR4A; x0 += k1;  x1 += ks2 + 1u;
    HR4B; x0 += ks2; x1 += k0  + 2u;
    HR4A; x0 += k0;  x1 += k1  + 3u;
    HR4B; x0 += k1;  x1 += ks2 + 4u;
    HR4A; x0 += ks2; x1 += k0  + 5u;
    *o0 = x0; *o1 = x1;
}
#undef HR4A
#undef HR4B

__device__ __forceinline__ uint32_t rotl32d(uint32_t x, int r) {
    return __funnelshift_l(x, x, r);
}

// counter hi word always 0; JAX partitionable random_bits -> x0 ^ x1
__device__ __forceinline__ uint32_t tf_bits(uint32_t k0, uint32_t k1, uint32_t ctr_lo) {
    uint32_t ks2 = k0 ^ k1 ^ 0x1BD11BDAu;
    uint32_t x0 = k0;
    uint32_t x1 = ctr_lo + k1;
#define R4A  x0+=x1; x1=rotl32d(x1,13); x1^=x0; x0+=x1; x1=rotl32d(x1,15); x1^=x0; \
             x0+=x1; x1=rotl32d(x1,26); x1^=x0; x0+=x1; x1=rotl32d(x1, 6); x1^=x0;
#define R4B  x0+=x1; x1=rotl32d(x1,17); x1^=x0; x0+=x1; x1=rotl32d(x1,29); x1^=x0; \
             x0+=x1; x1=rotl32d(x1,16); x1^=x0; x0+=x1; x1=rotl32d(x1,24); x1^=x0;
    R4A; x0 += k1;  x1 += ks2 + 1u;
    R4B; x0 += ks2; x1 += k0  + 2u;
    R4A; x0 += k0;  x1 += k1  + 3u;
    R4B; x0 += k1;  x1 += ks2 + 4u;
    R4A; x0 += ks2; x1 += k0  + 5u;
    return x0 ^ x1;
#undef R4A
#undef R4B
}

__device__ __forceinline__ float u01(uint32_t bits) {
    return __uint_as_float((bits >> 9) | 0x3f800000u) - 1.0f;
}

// ---------------- wv: circulant forward via nibble table + SHFL broadcast ----------------
// Packed accumulators: P0=(w0,w2) P1=(w4,w6) from row[d]; P2=(w1,w3) P3=(w5,w7) from row[d^32]
struct WvAcc { uint64_t P0, P1, P2, P3; };

__device__ __forceinline__ WvAcc compute_wv(uint32_t lo, uint32_t hi, int lane,
                                            const unsigned char* __restrict__ TwvRaw) {
    // lane n (n<16) owns nibble n of (lo|hi<<32), pre-scaled to its 1024-byte row offset
    uint32_t nib = (((lane < 8) ? (lo >> (4 * lane)) : (hi >> ((4 * lane) & 31))) & 15u) << 10;

    WvAcc A; A.P0 = A.P1 = A.P2 = A.P3 = 0ull;   // (0.0f, 0.0f)
    uint32_t d16 = (uint32_t)(((-lane) & 63) << 4);  // byte offset of float4 row entry
#pragma unroll
    for (int n = 0; n < 16; n++) {
        uint32_t rowoff = (uint32_t)__shfl_sync(0xffffffffu, (int)nib, n);
        ulonglong2 x = *(const ulonglong2*)(TwvRaw + rowoff + d16);
        ulonglong2 y = *(const ulonglong2*)(TwvRaw + rowoff + (d16 ^ 512u));
        addf32x2(A.P0, x.x); addf32x2(A.P1, x.y);
        addf32x2(A.P2, y.x); addf32x2(A.P3, y.y);
        d16 = (d16 + 64u) & 1023u;
    }
    return A;
}

// unpack to w[8]: w[2a]=wv[a,lane], w[2a+1]=wv[a,lane+32]
__device__ __forceinline__ void unpack_wv(const WvAcc& A, float* w) {
    unpack2(w[0], w[2], A.P0);
    unpack2(w[4], w[6], A.P1);
    unpack2(w[1], w[3], A.P2);
    unpack2(w[5], w[7], A.P3);
}

__device__ __forceinline__ float softplus_sum(const float* w, const float* cc) {
    float s = 0.0f;
#pragma unroll
    for (int a = 0; a < ALPHA; a++) {
#pragma unroll
        for (int hh = 0; hh < 2; hh++) {
            float z = w[a * 2 + hh] + cc[a];
            s += fmaxf(z, 0.0f) + log1pf(__expf(-fabsf(z)));
        }
    }
    return s;
}

// Bernoulli(sigmoid(z)) draw without divide: u < 1/(1+e^-z) <=> u*e^-z + u < 1
__device__ __forceinline__ int bern_sig(float u, float z) {
    float e = __expf(-z);
    return fmaf(u, e, u) < 1.0f;
}

// ---------------- main kernel: one warp per batch sample, 32 samples/block ----------------

__global__ void __launch_bounds__(TPB, 1)
rbm_kernel(const float* __restrict__ v_data, const float* __restrict__ kern,
           const float* __restrict__ bsc, const float* __restrict__ cvec,
           GibbsKeys keys) {
    extern __shared__ unsigned char smem_raw[];
    float2* Tt   = (float2*)smem_raw;                  // [256][64] pair (i, i+32)
    float4* kT4  = (float4*)(smem_raw + KT4_OFF);      // [64]
    float*  W    = (float*)(smem_raw + W_OFF);         // [16][64]
    float4* Twv  = (float4*)(smem_raw + TWV_OFF);      // [16][64]
    double* wsum = (double*)(smem_raw + WSUM_OFF);     // [WPB]
    const unsigned char* TwvRaw = smem_raw + TWV_OFF;
    const unsigned char* TtRaw  = smem_raw;

    const int tid = threadIdx.x;

    // ---- phase 1: W[s][d] = sum_a bit_a(s)*k[a][d]  and  kT4[d] = (k0..k3)[d] ----
    {
        if (tid < 16 * 64) {
            int s = tid >> 6, d = tid & 63;
            float acc = 0.0f;
#pragma unroll
            for (int a = 0; a < ALPHA; a++)
                if ((s >> a) & 1) acc += kern[a * NV + d];
            W[tid] = acc;
        }
        if (tid < 64)
            kT4[tid] = make_float4(kern[tid], kern[NV + tid], kern[2 * NV + tid], kern[3 * NV + tid]);
    }
    __syncthreads();

    // ---- phase 2a: Tt[idx8][e] (wh pair table) ----
    // idx8 = interleaved 2-bit fields (bits m, m+1 of each H[a])
    // Tt.x = W[slo][e] + W[shi][(e-1)&63]; Tt.y = same with ^32
    for (int idx = tid; idx < 256 * 64; idx += TPB) {
        int i8 = idx >> 6, e = idx & 63;
        int slo = (i8 & 1) | ((i8 >> 1) & 2) | ((i8 >> 2) & 4) | ((i8 >> 3) & 8);
        int shi = ((i8 >> 1) & 1) | ((i8 >> 2) & 2) | ((i8 >> 3) & 4) | ((i8 >> 4) & 8);
        int em1 = (e - 1) & 63;
        float x = W[slo * 64 + e] + W[shi * 64 + em1];
        float y = W[slo * 64 + (e ^ 32)] + W[shi * 64 + (em1 ^ 32)];
        Tt[idx] = make_float2(x, y);
    }

    // ---- phase 2b: Twv[s][d] = sum_{r in bits(s)} kT4[(d+r)&63]  (wv nibble table) ----
    if (tid < 16 * 64) {
        int s = tid >> 6, d = tid & 63;
        float4 acc = make_float4(0.f, 0.f, 0.f, 0.f);
#pragma unroll
        for (int r = 0; r < 4; r++) {
            if ((s >> r) & 1) {
                float4 k = kT4[(d + r) & 63];
                acc.x += k.x; acc.y += k.y; acc.z += k.z; acc.w += k.w;
            }
        }
        Twv[tid] = acc;
    }
    __syncthreads();

    const int lane = tid & 31;
    const int wid  = tid >> 5;
    const int b    = blockIdx.x * WPB + wid;

    const float bS = __ldg(bsc);
    float cc[ALPHA];
#pragma unroll
    for (int a = 0; a < ALPHA; a++) cc[a] = __ldg(cvec + a);

    // pack visible data into warp-uniform masks
    const float va = v_data[b * NV + lane];
    const float vb = v_data[b * NV + 32 + lane];
    uint32_t vlo = __ballot_sync(0xffffffffu, va > 0.5f);
    uint32_t vhi = __ballot_sync(0xffffffffu, vb > 0.5f);
    const uint32_t dlo = vlo, dhi = vhi;

    float w[8];

    // wv(V_data): shared by sp_d and step 0's hidden sampling
    {
        WvAcc A = compute_wv(dlo, dhi, lane, TwvRaw);
        unpack_wv(A, w);
    }
    const float sp_d = softplus_sum(w, cc);

    const uint32_t bb = (uint32_t)b * (ALPHA * NV) + (uint32_t)lane;  // hidden ctr base
    const uint32_t mv = (uint32_t)b * NV + (uint32_t)lane;            // visible ctr base
    const uint32_t ebOff0 = (uint32_t)(((lane - 1) & 63) << 3);       // byte offset of e within Tt row
    const int shsig = (2 * lane) & 31;                                // per-lane wh signature shift

#pragma unroll 1
    for (int t = 0; t < KSTEPS; t++) {
        // ---- sample hidden from current w (wv of current V) ----
        const uint32_t kh0 = keys.kh0[t], kh1 = keys.kh1[t];
        uint32_t hlo[ALPHA], hhi[ALPHA];
#pragma unroll
        for (int a = 0; a < ALPHA; a++) {
            const uint32_t mb = bb + (uint32_t)(a * NV);
            float u0 = u01(tf_bits(kh0, kh1, mb));
            float u1 = u01(tf_bits(kh0, kh1, mb + 32u));
            int h0 = bern_sig(u0, w[a * 2 + 0] + cc[a]);
            int h1 = bern_sig(u1, w[a * 2 + 1] + cc[a]);
            hlo[a] = __ballot_sync(0xffffffffu, h0);
            hhi[a] = __ballot_sync(0xffffffffu, h1);
        }

        // ---- per-lane wh signature: lane mm owns m = 2*mm, pre-scaled to 512B row ----
        // bits (m, m+1) of each channel; mm<16 from hlo (m<=30), mm>=16 from hhi
        uint32_t s0, s1, s2, s3;
        if (lane < 16) {
            s0 = hlo[0] >> shsig; s1 = hlo[1] >> shsig;
            s2 = hlo[2] >> shsig; s3 = hlo[3] >> shsig;
        } else {
            s0 = hhi[0] >> shsig; s1 = hhi[1] >> shsig;
            s2 = hhi[2] >> shsig; s3 = hhi[3] >> shsig;
        }
        uint32_t sigOff = ((s0 & 3u) | ((s1 & 3u) << 2) | ((s2 & 3u) << 4) | ((s3 & 3u) << 6)) << 9;

        // ---- wh: 32 dense iterations, SHFL-broadcast row offset, packed accumulate ----
        uint64_t WH = 0ull;  // (wh0, wh1)
#pragma unroll
        for (int mm = 0; mm < 32; mm++) {
            uint32_t rowoff = (uint32_t)__shfl_sync(0xffffffffu, (int)sigOff, mm);
            uint32_t eoff   = (ebOff0 - 16u * (uint32_t)mm) & 511u;
            addf32x2(WH, *(const uint64_t*)(TtRaw + rowoff + eoff));
        }
        float wh0, wh1;
        unpack2(wh0, wh1, WH);

        // ---- sample visible ----
        const uint32_t kv0 = keys.kv0[t], kv1 = keys.kv1[t];
        float u0 = u01(tf_bits(kv0, kv1, mv));
        float u1 = u01(tf_bits(kv0, kv1, mv + 32u));
        int n0 = bern_sig(u0, wh0 + bS);
        int n1 = bern_sig(u1, wh1 + bS);
        vlo = __ballot_sync(0xffffffffu, n0);
        vhi = __ballot_sync(0xffffffffu, n1);

        // ---- wv of new V (feeds next step's hidden sampling, or sp_m after t=9) ----
        WvAcc A = compute_wv(vlo, vhi, lane, TwvRaw);
        unpack_wv(A, w);
    }

    const float sp_m = softplus_sum(w, cc);

    // fe_data - fe_model = bS*(S_m - S_d) + (SP_m - SP_d)
    float x = sp_m - sp_d;
#pragma unroll
    for (int off = 16; off; off >>= 1) x += __shfl_xor_sync(0xffffffffu, x, off);

    if (lane == 0) {
        x += bS * (float)((__popc(vlo) + __popc(vhi)) - (__popc(dlo) + __popc(dhi)));
        wsum[wid] = (double)x;
    }
    __syncthreads();
    if (tid == 0) {
        double s = 0.0;
#pragma unroll
        for (int i = 0; i < WPB; i++) s += wsum[i];
        g_partials[blockIdx.x] = s;
    }
}

// ---------------- deterministic final reduction ----------------

__global__ void __launch_bounds__(256)
reduce_kernel(float* __restrict__ out) {
    __shared__ double sh[256];
    const int tid = threadIdx.x;
    double s = 0.0;
    for (int i = tid; i < NBLK; i += 256) s += g_partials[i];  // fixed order
    sh[tid] = s;
    __syncthreads();
    for (int off = 128; off; off >>= 1) {
        if (tid < off) sh[tid] += sh[tid + off];
        __syncthreads();
    }
    if (tid == 0) out[0] = (float)(sh[0] / (double)BATCH);
}

// ---------------- launch ----------------

extern "C" void kernel_launch(void* const* d_in, const int* in_sizes, int n_in,
                              void* d_out, int out_size) {
    (void)in_sizes; (void)n_in; (void)out_size;
    const float* v_data = (const float*)d_in[0];
    const float* kern   = (const float*)d_in[1];
    const float* bsc    = (const float*)d_in[2];
    const float* cvec   = (const float*)d_in[3];

    // JAX key schedule: key(42)=(0,42); fold-like split: keys[i]=threefry(k,(0,i))
    GibbsKeys keys;
    uint32_t k0 = 0u, k1 = 42u;
    for (int t = 0; t < KSTEPS; t++) {
        uint32_t n0, n1, h0, h1, w0, w1;
        tf2x32_host(k0, k1, 0u, 0u, &n0, &n1);
        tf2x32_host(k0, k1, 0u, 1u, &h0, &h1);
        tf2x32_host(k0, k1, 0u, 2u, &w0, &w1);
        keys.kh0[t] = h0; keys.kh1[t] = h1;
        keys.kv0[t] = w0; keys.kv1[t] = w1;
        k0 = n0; k1 = n1;
    }

    cudaFuncSetAttribute(rbm_kernel, cudaFuncAttributeMaxDynamicSharedMemorySize, SMEM_BYTES);
    rbm_kernel<<<NBLK, TPB, SMEM_BYTES>>>(v_data, kern, bsc, cvec, keys);
    reduce_kernel<<<1, 256>>>((float*)d_out);
}

// round 9
// speedup vs baseline: 3.5290x; 1.0358x over previous
#include <cuda_runtime.h>
#include <stdint.h>

// SymmetricRBM: B=65536 independent Gibbs chains, N=64 visible, ALPHA=4 hidden groups,
// circulant weights from kernel[4][64]. One warp per sample; binary states as u32-pair masks.
//
// Launch-constant tables in shared memory:
//   Tt  [256][64]  float2 : wh pair-signature table (8-bit sig over 4 channels x 2 bits)
//   Twv4[16][256]  float4 : wv nibble table, rows quadruplicated (period 64 entries) so
//                           both loads per iteration use immediate offsets (no wrap AND).
// Warp-uniform signatures built per-lane, broadcast via SHFL. Packed add.rn.f32x2
// accumulation; bias terms (c_vec, b_scalar) folded into accumulator init.

#define NV      64
#define ALPHA   4
#define BATCH   65536
#define KSTEPS  10
#define TPB     1024
#define WPB     32             // warps (=samples) per block
#define NBLK    (BATCH / WPB)  // 2048 blocks

// dynamic smem layout
#define T_BYTES    (256 * 64 * 8)            // float2 Tt[256][64]   = 131072
#define KT4_OFF    T_BYTES
#define KT4_BYTES  (64 * 16)                 // float4 kT4[64]       = 1024
#define W_OFF      (KT4_OFF + KT4_BYTES)
#define W_BYTES    (16 * 64 * 4)             // float  W[16][64]     = 4096
#define TWV_OFF    (W_OFF + W_BYTES)
#define TWV_BYTES  (16 * 256 * 16)           // float4 Twv4[16][256] = 65536
#define WSUM_OFF   (TWV_OFF + TWV_BYTES)
#define WSUM_BYTES (WPB * 8)
#define SMEM_BYTES (WSUM_OFF + WSUM_BYTES)   // 201984

struct GibbsKeys {
    uint32_t kh0[KSTEPS], kh1[KSTEPS];
    uint32_t kv0[KSTEPS], kv1[KSTEPS];
};

__device__ double g_partials[NBLK];

// ---------------- packed f32x2 helpers ----------------

__device__ __forceinline__ void addf32x2(uint64_t& acc, uint64_t v) {
    asm("add.rn.f32x2 %0, %0, %1;" : "+l"(acc) : "l"(v));
}
__device__ __forceinline__ void unpack2(float& lo, float& hi, uint64_t v) {
    uint32_t a, b;
    asm("mov.b64 {%0, %1}, %2;" : "=r"(a), "=r"(b) : "l"(v));
    lo = __uint_as_float(a); hi = __uint_as_float(b);
}
__device__ __forceinline__ uint64_t packf2(float lo, float hi) {
    uint64_t r;
    asm("mov.b64 %0, {%1, %2};" : "=l"(r)
        : "r"(__float_as_uint(lo)), "r"(__float_as_uint(hi)));
    return r;
}

// ---------------- Threefry-2x32 (20 rounds), JAX-compatible ----------------

__host__ static uint32_t rotl32h(uint32_t x, int r) {
    return (x << r) | (x >> (32 - r));
}

__host__ static void tf2x32_host(uint32_t k0, uint32_t k1, uint32_t c0, uint32_t c1,
                                 uint32_t* o0, uint32_t* o1) {
    uint32_t ks2 = k0 ^ k1 ^ 0x1BD11BDAu;
    uint32_t x0 = c0 + k0, x1 = c1 + k1;
#define HR4A x0+=x1; x1=rotl32h(x1,13); x1^=x0; x0+=x1; x1=rotl32h(x1,15); x1^=x0; \
             x0+=x1; x1=rotl32h(x1,26); x1^=x0; x0+=x1; x1=rotl32h(x1, 6); x1^=x0;
#define HR4B x0+=x1; x1=rotl32h(x1,17); x1^=x0; x0+=x1; x1=rotl32h(x1,29); x1^=x0; \
             x0+=x1; x1=rotl32h(x1,16); x1^=x0; x0+=x1; x1=rotl32h(x1,24); x1^=x0;
    HR4A; x0 += k1;  x1 += ks2 + 1u;
    HR4B; x0 += ks2; x1 += k0  + 2u;
    HR4A; x0 += k0;  x1 += k1  + 3u;
    HR4B; x0 += k1;  x1 += ks2 + 4u;
    HR4A; x0 += ks2; x1 += k0  + 5u;
    *o0 = x0; *o1 = x1;
}
#undef HR4A
#undef HR4B

__device__ __forceinline__ uint32_t rotl32d(uint32_t x, int r) {
    return __funnelshift_l(x, x, r);
}

// counter hi word always 0; JAX partitionable random_bits -> x0 ^ x1
__device__ __forceinline__ uint32_t tf_bits(uint32_t k0, uint32_t k1, uint32_t ctr_lo) {
    uint32_t ks2 = k0 ^ k1 ^ 0x1BD11BDAu;
    uint32_t x0 = k0;
    uint32_t x1 = ctr_lo + k1;
#define R4A  x0+=x1; x1=rotl32d(x1,13); x1^=x0; x0+=x1; x1=rotl32d(x1,15); x1^=x0; \
             x0+=x1; x1=rotl32d(x1,26); x1^=x0; x0+=x1; x1=rotl32d(x1, 6); x1^=x0;
#define R4B  x0+=x1; x1=rotl32d(x1,17); x1^=x0; x0+=x1; x1=rotl32d(x1,29); x1^=x0; \
             x0+=x1; x1=rotl32d(x1,16); x1^=x0; x0+=x1; x1=rotl32d(x1,24); x1^=x0;
    R4A; x0 += k1;  x1 += ks2 + 1u;
    R4B; x0 += ks2; x1 += k0  + 2u;
    R4A; x0 += k0;  x1 += k1  + 3u;
    R4B; x0 += k1;  x1 += ks2 + 4u;
    R4A; x0 += ks2; x1 += k0  + 5u;
    return x0 ^ x1;
#undef R4A
#undef R4B
}

__device__ __forceinline__ float u01(uint32_t bits) {
    return __uint_as_float((bits >> 9) | 0x3f800000u) - 1.0f;
}

// ---------------- wv: circulant forward via quadruplicated nibble table ----------------
// Packed accumulators (bias pre-seeded): P0=(w0,w2) P1=(w4,w6) from row[d];
// P2=(w1,w3) P3=(w5,w7) from row[d+512 bytes] (== d^32 entries, period-1024 content).
struct WvAcc { uint64_t P0, P1, P2, P3; };

__device__ __forceinline__ WvAcc compute_wv(uint32_t lo, uint32_t hi, int lane,
                                            const unsigned char* __restrict__ TwvRaw,
                                            uint64_t CC01, uint64_t CC23) {
    // lane n (n<16) owns nibble n of (lo|hi<<32), pre-scaled to its 4096-byte row offset
    uint32_t nib = (((lane < 8) ? (lo >> (4 * lane)) : (hi >> ((4 * lane) & 31))) & 15u) << 12;

    WvAcc A; A.P0 = CC01; A.P1 = CC23; A.P2 = CC01; A.P3 = CC23;
    const unsigned char* pbase = TwvRaw + (uint32_t)(((-lane) & 63) << 4);
#pragma unroll
    for (int n = 0; n < 16; n++) {
        uint32_t rowoff = (uint32_t)__shfl_sync(0xffffffffu, (int)nib, n);
        const unsigned char* p = pbase + rowoff;
        ulonglong2 x = *(const ulonglong2*)(p + 64 * n);
        ulonglong2 y = *(const ulonglong2*)(p + 64 * n + 512);
        addf32x2(A.P0, x.x); addf32x2(A.P1, x.y);
        addf32x2(A.P2, y.x); addf32x2(A.P3, y.y);
    }
    return A;
}

// unpack to w[8]: w[2a]=wv[a,lane]+cc[a], w[2a+1]=wv[a,lane+32]+cc[a]
__device__ __forceinline__ void unpack_wv(const WvAcc& A, float* w) {
    unpack2(w[0], w[2], A.P0);
    unpack2(w[4], w[6], A.P1);
    unpack2(w[1], w[3], A.P2);
    unpack2(w[5], w[7], A.P3);
}

// w already includes cc
__device__ __forceinline__ float softplus_sum(const float* w) {
    float s = 0.0f;
#pragma unroll
    for (int q = 0; q < 8; q++) {
        float z = w[q];
        s += fmaxf(z, 0.0f) + log1pf(__expf(-fabsf(z)));
    }
    return s;
}

// Bernoulli(sigmoid(z)) draw without divide: u < 1/(1+e^-z) <=> u*e^-z + u < 1
__device__ __forceinline__ int bern_sig(float u, float z) {
    float e = __expf(-z);
    return fmaf(u, e, u) < 1.0f;
}

// ---------------- main kernel: one warp per batch sample, 32 samples/block ----------------

__global__ void __launch_bounds__(TPB, 1)
rbm_kernel(const float* __restrict__ v_data, const float* __restrict__ kern,
           const float* __restrict__ bsc, const float* __restrict__ cvec,
           GibbsKeys keys) {
    extern __shared__ unsigned char smem_raw[];
    float2* Tt   = (float2*)smem_raw;                  // [256][64] pair (i, i+32)
    float4* kT4  = (float4*)(smem_raw + KT4_OFF);      // [64]
    float*  W    = (float*)(smem_raw + W_OFF);         // [16][64]
    float4* Twv4 = (float4*)(smem_raw + TWV_OFF);      // [16][256] quadruplicated rows
    double* wsum = (double*)(smem_raw + WSUM_OFF);     // [WPB]
    const unsigned char* TwvRaw = smem_raw + TWV_OFF;
    const unsigned char* TtRaw  = smem_raw;

    const int tid = threadIdx.x;

    // ---- phase 1: W[s][d] = sum_a bit_a(s)*k[a][d]  and  kT4[d] = (k0..k3)[d] ----
    {
        if (tid < 16 * 64) {
            int s = tid >> 6, d = tid & 63;
            float acc = 0.0f;
#pragma unroll
            for (int a = 0; a < ALPHA; a++)
                if ((s >> a) & 1) acc += kern[a * NV + d];
            W[tid] = acc;
        }
        if (tid < 64)
            kT4[tid] = make_float4(kern[tid], kern[NV + tid], kern[2 * NV + tid], kern[3 * NV + tid]);
    }
    __syncthreads();

    // ---- phase 2a: Tt[idx8][e] (wh pair table) ----
    // idx8 = interleaved 2-bit fields (bits m, m+1 of each H[a])
    // Tt.x = W[slo][e] + W[shi][(e-1)&63]; Tt.y = same with ^32
    for (int idx = tid; idx < 256 * 64; idx += TPB) {
        int i8 = idx >> 6, e = idx & 63;
        int slo = (i8 & 1) | ((i8 >> 1) & 2) | ((i8 >> 2) & 4) | ((i8 >> 3) & 8);
        int shi = ((i8 >> 1) & 1) | ((i8 >> 2) & 2) | ((i8 >> 3) & 4) | ((i8 >> 4) & 8);
        int em1 = (e - 1) & 63;
        float x = W[slo * 64 + e] + W[shi * 64 + em1];
        float y = W[slo * 64 + (e ^ 32)] + W[shi * 64 + (em1 ^ 32)];
        Tt[idx] = make_float2(x, y);
    }

    // ---- phase 2b: Twv4[s][i] = sum_{r in bits(s)} kT4[((i&63)+r)&63], i in [0,256) ----
    // (rows quadruplicated: content period 64 entries = 1024 bytes)
    for (int idx = tid; idx < 16 * 256; idx += TPB) {
        int s = idx >> 8, d = idx & 63;
        float4 acc = make_float4(0.f, 0.f, 0.f, 0.f);
#pragma unroll
        for (int r = 0; r < 4; r++) {
            if ((s >> r) & 1) {
                float4 k = kT4[(d + r) & 63];
                acc.x += k.x; acc.y += k.y; acc.z += k.z; acc.w += k.w;
            }
        }
        Twv4[idx] = acc;
    }
    __syncthreads();

    const int lane = tid & 31;
    const int wid  = tid >> 5;
    const int b    = blockIdx.x * WPB + wid;

    const float bS = __ldg(bsc);
    const uint64_t CC01 = packf2(__ldg(cvec + 0), __ldg(cvec + 1));
    const uint64_t CC23 = packf2(__ldg(cvec + 2), __ldg(cvec + 3));
    const uint64_t BSS  = packf2(bS, bS);

    // pack visible data into warp-uniform masks
    const float va = v_data[b * NV + lane];
    const float vb = v_data[b * NV + 32 + lane];
    uint32_t vlo = __ballot_sync(0xffffffffu, va > 0.5f);
    uint32_t vhi = __ballot_sync(0xffffffffu, vb > 0.5f);
    const uint32_t dlo = vlo, dhi = vhi;

    float w[8];

    // wv(V_data)+cc: shared by sp_d and step 0's hidden sampling
    {
        WvAcc A = compute_wv(dlo, dhi, lane, TwvRaw, CC01, CC23);
        unpack_wv(A, w);
    }
    const float sp_d = softplus_sum(w);

    const uint32_t bb = (uint32_t)b * (ALPHA * NV) + (uint32_t)lane;  // hidden ctr base
    const uint32_t mv = (uint32_t)b * NV + (uint32_t)lane;            // visible ctr base
    const uint32_t ebOff0 = (uint32_t)(((lane - 1) & 63) << 3);       // byte offset of e within Tt row
    const int shsig = (2 * lane) & 31;                                // per-lane wh signature shift

#pragma unroll 1
    for (int t = 0; t < KSTEPS; t++) {
        // ---- sample hidden from current w (wv of current V, cc included) ----
        const uint32_t kh0 = keys.kh0[t], kh1 = keys.kh1[t];
        uint32_t hlo[ALPHA], hhi[ALPHA];
#pragma unroll
        for (int a = 0; a < ALPHA; a++) {
            const uint32_t mb = bb + (uint32_t)(a * NV);
            float u0 = u01(tf_bits(kh0, kh1, mb));
            float u1 = u01(tf_bits(kh0, kh1, mb + 32u));
            int h0 = bern_sig(u0, w[a * 2 + 0]);
            int h1 = bern_sig(u1, w[a * 2 + 1]);
            hlo[a] = __ballot_sync(0xffffffffu, h0);
            hhi[a] = __ballot_sync(0xffffffffu, h1);
        }

        // ---- per-lane wh signature: lane mm owns m = 2*mm, pre-scaled to 512B row ----
        uint32_t s0, s1, s2, s3;
        if (lane < 16) {
            s0 = hlo[0] >> shsig; s1 = hlo[1] >> shsig;
            s2 = hlo[2] >> shsig; s3 = hlo[3] >> shsig;
        } else {
            s0 = hhi[0] >> shsig; s1 = hhi[1] >> shsig;
            s2 = hhi[2] >> shsig; s3 = hhi[3] >> shsig;
        }
        uint32_t sigOff = ((s0 & 3u) | ((s1 & 3u) << 2) | ((s2 & 3u) << 4) | ((s3 & 3u) << 6)) << 9;

        // ---- wh: 32 dense iterations, SHFL-broadcast row offset, packed accumulate ----
        uint64_t WH = BSS;  // (wh0+bS, wh1+bS) when done
#pragma unroll
        for (int mm = 0; mm < 32; mm++) {
            uint32_t rowoff = (uint32_t)__shfl_sync(0xffffffffu, (int)sigOff, mm);
            uint32_t eoff   = (ebOff0 - 16u * (uint32_t)mm) & 511u;
            addf32x2(WH, *(const uint64_t*)(TtRaw + rowoff + eoff));
        }
        float wh0, wh1;
        unpack2(wh0, wh1, WH);

        // ---- sample visible ----
        const uint32_t kv0 = keys.kv0[t], kv1 = keys.kv1[t];
        float u0 = u01(tf_bits(kv0, kv1, mv));
        float u1 = u01(tf_bits(kv0, kv1, mv + 32u));
        int n0 = bern_sig(u0, wh0);
        int n1 = bern_sig(u1, wh1);
        vlo = __ballot_sync(0xffffffffu, n0);
        vhi = __ballot_sync(0xffffffffu, n1);

        // ---- wv of new V (feeds next step's hidden sampling, or sp_m after t=9) ----
        WvAcc A = compute_wv(vlo, vhi, lane, TwvRaw, CC01, CC23);
        unpack_wv(A, w);
    }

    const float sp_m = softplus_sum(w);

    // fe_data - fe_model = bS*(S_m - S_d) + (SP_m - SP_d)
    float x = sp_m - sp_d;
#pragma unroll
    for (int off = 16; off; off >>= 1) x += __shfl_xor_sync(0xffffffffu, x, off);

    if (lane == 0) {
        x += bS * (float)((__popc(vlo) + __popc(vhi)) - (__popc(dlo) + __popc(dhi)));
        wsum[wid] = (double)x;
    }
    __syncthreads();
    if (tid == 0) {
        double s = 0.0;
#pragma unroll
        for (int i = 0; i < WPB; i++) s += wsum[i];
        g_partials[blockIdx.x] = s;
    }
}

// ---------------- deterministic final reduction ----------------

__global__ void __launch_bounds__(256)
reduce_kernel(float* __restrict__ out) {
    __shared__ double sh[256];
    const int tid = threadIdx.x;
    double s = 0.0;
    for (int i = tid; i < NBLK; i += 256) s += g_partials[i];  // fixed order
    sh[tid] = s;
    __syncthreads();
    for (int off = 128; off; off >>= 1) {
        if (tid < off) sh[tid] += sh[tid + off];
        __syncthreads();
    }
    if (tid == 0) out[0] = (float)(sh[0] / (double)BATCH);
}

// ---------------- launch ----------------

extern "C" void kernel_launch(void* const* d_in, const int* in_sizes, int n_in,
                              void* d_out, int out_size) {
    (void)in_sizes; (void)n_in; (void)out_size;
    const float* v_data = (const float*)d_in[0];
    const float* kern   = (const float*)d_in[1];
    const float* bsc    = (const float*)d_in[2];
    const float* cvec   = (const float*)d_in[3];

    // JAX key schedule: key(42)=(0,42); fold-like split: keys[i]=threefry(k,(0,i))
    GibbsKeys keys;
    uint32_t k0 = 0u, k1 = 42u;
    for (int t = 0; t < KSTEPS; t++) {
        uint32_t n0, n1, h0, h1, w0, w1;
        tf2x32_host(k0, k1, 0u, 0u, &n0, &n1);
        tf2x32_host(k0, k1, 0u, 1u, &h0, &h1);
        tf2x32_host(k0, k1, 0u, 2u, &w0, &w1);
        keys.kh0[t] = h0; keys.kh1[t] = h1;
        keys.kv0[t] = w0; keys.kv1[t] = w1;
        k0 = n0; k1 = n1;
    }

    cudaFuncSetAttribute(rbm_kernel, cudaFuncAttributeMaxDynamicSharedMemorySize, SMEM_BYTES);
    rbm_kernel<<<NBLK, TPB, SMEM_BYTES>>>(v_data, kern, bsc, cvec, keys);
    reduce_kernel<<<1, 256>>>((float*)d_out);
}

// round 11
// speedup vs baseline: 3.5520x; 1.0065x over previous
#include <cuda_runtime.h>
#include <stdint.h>

// SymmetricRBM: B=65536 independent Gibbs chains, N=64 visible, ALPHA=4 hidden groups,
// circulant weights from kernel[4][64]. One warp per sample; binary states as u32-pair masks.
//
// Launch-constant tables in shared memory, PRE-SCALED by -log2(e) so accumulators
// directly produce the MUFU.EX2 argument for exp(-z) (no per-draw FMUL):
//   Tt  [256][64]  float2 : wh pair-signature table (8-bit sig over 4 channels x 2 bits)
//   Twv4[16][256]  float4 : wv nibble table, rows quadruplicated (imm offsets, no wrap AND)
// Softplus evaluated in base-2 from the scaled accumulators.

#define NV      64
#define ALPHA   4
#define BATCH   65536
#define KSTEPS  10
#define TPB     1024
#define WPB     32             // warps (=samples) per block
#define NBLK    (BATCH / WPB)  // 2048 blocks

#define NEG_LOG2E (-1.4426950408889634f)
#define LN2F      (0.6931471805599453f)

// dynamic smem layout
#define T_BYTES    (256 * 64 * 8)            // float2 Tt[256][64]   = 131072
#define KT4_OFF    T_BYTES
#define KT4_BYTES  (64 * 16)                 // float4 kT4[64]       = 1024
#define W_OFF      (KT4_OFF + KT4_BYTES)
#define W_BYTES    (16 * 64 * 4)             // float  W[16][64]     = 4096
#define TWV_OFF    (W_OFF + W_BYTES)
#define TWV_BYTES  (16 * 256 * 16)           // float4 Twv4[16][256] = 65536
#define WSUM_OFF   (TWV_OFF + TWV_BYTES)
#define WSUM_BYTES (WPB * 8)
#define SMEM_BYTES (WSUM_OFF + WSUM_BYTES)   // 201984

struct GibbsKeys {
    uint32_t kh0[KSTEPS], kh1[KSTEPS];
    uint32_t kv0[KSTEPS], kv1[KSTEPS];
};

__device__ double g_partials[NBLK];

// ---------------- packed f32x2 helpers ----------------

__device__ __forceinline__ void addf32x2(uint64_t& acc, uint64_t v) {
    asm("add.rn.f32x2 %0, %0, %1;" : "+l"(acc) : "l"(v));
}
__device__ __forceinline__ void unpack2(float& lo, float& hi, uint64_t v) {
    uint32_t a, b;
    asm("mov.b64 {%0, %1}, %2;" : "=r"(a), "=r"(b) : "l"(v));
    lo = __uint_as_float(a); hi = __uint_as_float(b);
}
__device__ __forceinline__ uint64_t packf2(float lo, float hi) {
    uint64_t r;
    asm("mov.b64 %0, {%1, %2};" : "=l"(r)
        : "r"(__float_as_uint(lo)), "r"(__float_as_uint(hi)));
    return r;
}
__device__ __forceinline__ float ex2f(float x) {
    float r;
    asm("ex2.approx.f32 %0, %1;" : "=f"(r) : "f"(x));
    return r;
}

// ---------------- Threefry-2x32 (20 rounds), JAX-compatible ----------------

__host__ static uint32_t rotl32h(uint32_t x, int r) {
    return (x << r) | (x >> (32 - r));
}

__host__ static void tf2x32_host(uint32_t k0, uint32_t k1, uint32_t c0, uint32_t c1,
                                 uint32_t* o0, uint32_t* o1) {
    uint32_t ks2 = k0 ^ k1 ^ 0x1BD11BDAu;
    uint32_t x0 = c0 + k0, x1 = c1 + k1;
#define HR4A x0+=x1; x1=rotl32h(x1,13); x1^=x0; x0+=x1; x1=rotl32h(x1,15); x1^=x0; \
             x0+=x1; x1=rotl32h(x1,26); x1^=x0; x0+=x1; x1=rotl32h(x1, 6); x1^=x0;
#define HR4B x0+=x1; x1=rotl32h(x1,17); x1^=x0; x0+=x1; x1=rotl32h(x1,29); x1^=x0; \
             x0+=x1; x1=rotl32h(x1,16); x1^=x0; x0+=x1; x1=rotl32h(x1,24); x1^=x0;
    HR4A; x0 += k1;  x1 += ks2 + 1u;
    HR4B; x0 += ks2; x1 += k0  + 2u;
    HR4A; x0 += k0;  x1 += k1  + 3u;
    HR4B; x0 += k1;  x1 += ks2 + 4u;
    HR4A; x0 += ks2; x1 += k0  + 5u;
    *o0 = x0; *o1 = x1;
}
#undef HR4A
#undef HR4B

__device__ __forceinline__ uint32_t rotl32d(uint32_t x, int r) {
    return __funnelshift_l(x, x, r);
}

// counter hi word always 0; JAX partitionable random_bits -> x0 ^ x1
__device__ __forceinline__ uint32_t tf_bits(uint32_t k0, uint32_t k1, uint32_t ctr_lo) {
    uint32_t ks2 = k0 ^ k1 ^ 0x1BD11BDAu;
    uint32_t x0 = k0;
    uint32_t x1 = ctr_lo + k1;
#define R4A  x0+=x1; x1=rotl32d(x1,13); x1^=x0; x0+=x1; x1=rotl32d(x1,15); x1^=x0; \
             x0+=x1; x1=rotl32d(x1,26); x1^=x0; x0+=x1; x1=rotl32d(x1, 6); x1^=x0;
#define R4B  x0+=x1; x1=rotl32d(x1,17); x1^=x0; x0+=x1; x1=rotl32d(x1,29); x1^=x0; \
             x0+=x1; x1=rotl32d(x1,16); x1^=x0; x0+=x1; x1=rotl32d(x1,24); x1^=x0;
    R4A; x0 += k1;  x1 += ks2 + 1u;
    R4B; x0 += ks2; x1 += k0  + 2u;
    R4A; x0 += k0;  x1 += k1  + 3u;
    R4B; x0 += k1;  x1 += ks2 + 4u;
    R4A; x0 += ks2; x1 += k0  + 5u;
    return x0 ^ x1;
#undef R4A
#undef R4B
}

__device__ __forceinline__ float u01(uint32_t bits) {
    return __uint_as_float((bits >> 9) | 0x3f800000u) - 1.0f;
}

// ---------------- wv: circulant forward via quadruplicated nibble table ----------------
// Accumulators hold SCALED values wp = -log2e*(wv+cc):
// P0=(wp0,wp2) P1=(wp4,wp6) from row[d]; P2=(wp1,wp3) P3=(wp5,wp7) from row[d+512B].
struct WvAcc { uint64_t P0, P1, P2, P3; };

__device__ __forceinline__ WvAcc compute_wv(uint32_t lo, uint32_t hi, int lane,
                                            const unsigned char* __restrict__ TwvRaw,
                                            uint64_t CC01, uint64_t CC23) {
    // lane n (n<16) owns nibble n of (lo|hi<<32), pre-scaled to its 4096-byte row offset
    uint32_t nib = (((lane < 8) ? (lo >> (4 * lane)) : (hi >> ((4 * lane) & 31))) & 15u) << 12;

    WvAcc A; A.P0 = CC01; A.P1 = CC23; A.P2 = CC01; A.P3 = CC23;
    const unsigned char* pbase = TwvRaw + (uint32_t)(((-lane) & 63) << 4);
#pragma unroll
    for (int n = 0; n < 16; n++) {
        uint32_t rowoff = (uint32_t)__shfl_sync(0xffffffffu, (int)nib, n);
        const unsigned char* p = pbase + rowoff;
        ulonglong2 x = *(const ulonglong2*)(p + 64 * n);
        ulonglong2 y = *(const ulonglong2*)(p + 64 * n + 512);
        addf32x2(A.P0, x.x); addf32x2(A.P1, x.y);
        addf32x2(A.P2, y.x); addf32x2(A.P3, y.y);
    }
    return A;
}

// unpack to w[8] (scaled space): w[2a]=wp[a,lane], w[2a+1]=wp[a,lane+32]
__device__ __forceinline__ void unpack_wv(const WvAcc& A, float* w) {
    unpack2(w[0], w[2], A.P0);
    unpack2(w[4], w[6], A.P1);
    unpack2(w[1], w[3], A.P2);
    unpack2(w[5], w[7], A.P3);
}

// softplus sum from SCALED wp = -log2e*z:
//   softplus(z) = ln2*max(-wp,0) + log1p(2^(-|wp|)),  -|wp| = min(wp,-wp)
__device__ __forceinline__ float softplus_sum(const float* w) {
    float s = 0.0f;
#pragma unroll
    for (int q = 0; q < 8; q++) {
        float wp = w[q];
        float nw = -wp;
        float t  = ex2f(fminf(wp, nw));
        s += fmaf(fmaxf(nw, 0.0f), LN2F, log1pf(t));
    }
    return s;
}

// Bernoulli(sigmoid(z)) draw from scaled wp = -log2e*z:
// e = exp(-z) = 2^wp; u < 1/(1+e) <=> u*e + u < 1
__device__ __forceinline__ int bern_sig(float u, float wp) {
    float e = ex2f(wp);
    return fmaf(u, e, u) < 1.0f;
}

// ---------------- main kernel: one warp per batch sample, 32 samples/block ----------------

__global__ void __launch_bounds__(TPB, 1)
rbm_kernel(const float* __restrict__ v_data, const float* __restrict__ kern,
           const float* __restrict__ bsc, const float* __restrict__ cvec,
           GibbsKeys keys) {
    extern __shared__ unsigned char smem_raw[];
    float2* Tt   = (float2*)smem_raw;                  // [256][64] pair (i, i+32), SCALED
    float4* kT4  = (float4*)(smem_raw + KT4_OFF);      // [64]
    float*  W    = (float*)(smem_raw + W_OFF);         // [16][64]
    float4* Twv4 = (float4*)(smem_raw + TWV_OFF);      // [16][256] quadruplicated, SCALED
    double* wsum = (double*)(smem_raw + WSUM_OFF);     // [WPB]
    const unsigned char* TwvRaw = smem_raw + TWV_OFF;
    const unsigned char* TtRaw  = smem_raw;

    const int tid = threadIdx.x;

    // ---- phase 1: W[s][d] = sum_a bit_a(s)*k[a][d] (unscaled) and kT4[d] ----
    {
        if (tid < 16 * 64) {
            int s = tid >> 6, d = tid & 63;
            float acc = 0.0f;
#pragma unroll
            for (int a = 0; a < ALPHA; a++)
                if ((s >> a) & 1) acc += kern[a * NV + d];
            W[tid] = acc;
        }
        if (tid < 64)
            kT4[tid] = make_float4(kern[tid], kern[NV + tid], kern[2 * NV + tid], kern[3 * NV + tid]);
    }
    __syncthreads();

    // ---- phase 2a: Tt[idx8][e] (wh pair table), scaled by -log2e ----
    for (int idx = tid; idx < 256 * 64; idx += TPB) {
        int i8 = idx >> 6, e = idx & 63;
        int slo = (i8 & 1) | ((i8 >> 1) & 2) | ((i8 >> 2) & 4) | ((i8 >> 3) & 8);
        int shi = ((i8 >> 1) & 1) | ((i8 >> 2) & 2) | ((i8 >> 3) & 4) | ((i8 >> 4) & 8);
        int em1 = (e - 1) & 63;
        float x = W[slo * 64 + e] + W[shi * 64 + em1];
        float y = W[slo * 64 + (e ^ 32)] + W[shi * 64 + (em1 ^ 32)];
        Tt[idx] = make_float2(NEG_LOG2E * x, NEG_LOG2E * y);
    }

    // ---- phase 2b: Twv4[s][i] = -log2e * sum_{r in bits(s)} kT4[((i&63)+r)&63] ----
    for (int idx = tid; idx < 16 * 256; idx += TPB) {
        int s = idx >> 8, d = idx & 63;
        float4 acc = make_float4(0.f, 0.f, 0.f, 0.f);
#pragma unroll
        for (int r = 0; r < 4; r++) {
            if ((s >> r) & 1) {
                float4 k = kT4[(d + r) & 63];
                acc.x += k.x; acc.y += k.y; acc.z += k.z; acc.w += k.w;
            }
        }
        Twv4[idx] = make_float4(NEG_LOG2E * acc.x, NEG_LOG2E * acc.y,
                                NEG_LOG2E * acc.z, NEG_LOG2E * acc.w);
    }
    __syncthreads();

    const int lane = tid & 31;
    const int wid  = tid >> 5;
    const int b    = blockIdx.x * WPB + wid;

    const float bS = __ldg(bsc);
    const float sc_bS = NEG_LOG2E * bS;
    const uint64_t CC01 = packf2(NEG_LOG2E * __ldg(cvec + 0), NEG_LOG2E * __ldg(cvec + 1));
    const uint64_t CC23 = packf2(NEG_LOG2E * __ldg(cvec + 2), NEG_LOG2E * __ldg(cvec + 3));
    const uint64_t BSS  = packf2(sc_bS, sc_bS);

    // pack visible data into warp-uniform masks
    const float va = v_data[b * NV + lane];
    const float vb = v_data[b * NV + 32 + lane];
    uint32_t vlo = __ballot_sync(0xffffffffu, va > 0.5f);
    uint32_t vhi = __ballot_sync(0xffffffffu, vb > 0.5f);
    const uint32_t dlo = vlo, dhi = vhi;

    float w[8];

    // scaled wv(V_data)+cc: shared by sp_d and step 0's hidden sampling
    {
        WvAcc A = compute_wv(dlo, dhi, lane, TwvRaw, CC01, CC23);
        unpack_wv(A, w);
    }
    const float sp_d = softplus_sum(w);

    const uint32_t bb = (uint32_t)b * (ALPHA * NV) + (uint32_t)lane;  // hidden ctr base
    const uint32_t mv = (uint32_t)b * NV + (uint32_t)lane;            // visible ctr base
    const uint32_t ebOff0 = (uint32_t)(((lane - 1) & 63) << 3);       // byte offset of e within Tt row
    const int shsig = (2 * lane) & 31;                                // per-lane wh signature shift

#pragma unroll 1
    for (int t = 0; t < KSTEPS; t++) {
        // ---- sample hidden from scaled w ----
        const uint32_t kh0 = keys.kh0[t], kh1 = keys.kh1[t];
        uint32_t hlo[ALPHA], hhi[ALPHA];
#pragma unroll
        for (int a = 0; a < ALPHA; a++) {
            const uint32_t mb = bb + (uint32_t)(a * NV);
            float u0 = u01(tf_bits(kh0, kh1, mb));
            float u1 = u01(tf_bits(kh0, kh1, mb + 32u));
            int h0 = bern_sig(u0, w[a * 2 + 0]);
            int h1 = bern_sig(u1, w[a * 2 + 1]);
            hlo[a] = __ballot_sync(0xffffffffu, h0);
            hhi[a] = __ballot_sync(0xffffffffu, h1);
        }

        // ---- per-lane wh signature (IMAD combine), pre-scaled to 512B row ----
        uint32_t s0, s1, s2, s3;
        if (lane < 16) {
            s0 = hlo[0] >> shsig; s1 = hlo[1] >> shsig;
            s2 = hlo[2] >> shsig; s3 = hlo[3] >> shsig;
        } else {
            s0 = hhi[0] >> shsig; s1 = hhi[1] >> shsig;
            s2 = hhi[2] >> shsig; s3 = hhi[3] >> shsig;
        }
        uint32_t sigOff = ((s0 & 3u) + (s1 & 3u) * 4u + (s2 & 3u) * 16u + (s3 & 3u) * 64u) * 512u;

        // ---- wh: 32 dense iterations, SHFL-broadcast row offset, dual packed accums ----
        uint64_t WHa = BSS, WHb = 0ull;  // scaled: -log2e*(wh+bS) when merged
#pragma unroll
        for (int mm = 0; mm < 32; mm += 2) {
            uint32_t ro0 = (uint32_t)__shfl_sync(0xffffffffu, (int)sigOff, mm);
            uint32_t e0  = (ebOff0 - 16u * (uint32_t)mm) & 511u;
            addf32x2(WHa, *(const uint64_t*)(TtRaw + ro0 + e0));
            uint32_t ro1 = (uint32_t)__shfl_sync(0xffffffffu, (int)sigOff, mm + 1);
            uint32_t e1  = (ebOff0 - 16u * (uint32_t)(mm + 1)) & 511u;
            addf32x2(WHb, *(const uint64_t*)(TtRaw + ro1 + e1));
        }
        addf32x2(WHa, WHb);
        float wh0, wh1;
        unpack2(wh0, wh1, WHa);

        // ---- sample visible ----
        const uint32_t kv0 = keys.kv0[t], kv1 = keys.kv1[t];
        float u0 = u01(tf_bits(kv0, kv1, mv));
        float u1 = u01(tf_bits(kv0, kv1, mv + 32u));
        int n0 = bern_sig(u0, wh0);
        int n1 = bern_sig(u1, wh1);
        vlo = __ballot_sync(0xffffffffu, n0);
        vhi = __ballot_sync(0xffffffffu, n1);

        // ---- scaled wv of new V (next step's hidden sampling, or sp_m after t=9) ----
        WvAcc A = compute_wv(vlo, vhi, lane, TwvRaw, CC01, CC23);
        unpack_wv(A, w);
    }

    const float sp_m = softplus_sum(w);

    // fe_data - fe_model = bS*(S_m - S_d) + (SP_m - SP_d)
    float x = sp_m - sp_d;
#pragma unroll
    for (int off = 16; off; off >>= 1) x += __shfl_xor_sync(0xffffffffu, x, off);

    if (lane == 0) {
        x += bS * (float)((__popc(vlo) + __popc(vhi)) - (__popc(dlo) + __popc(dhi)));
        wsum[wid] = (double)x;
    }
    __syncthreads();
    if (tid == 0) {
        double s = 0.0;
#pragma unroll
        for (int i = 0; i < WPB; i++) s += wsum[i];
        g_partials[blockIdx.x] = s;
    }
}

// ---------------- deterministic final reduction ----------------

__global__ void __launch_bounds__(256)
reduce_kernel(float* __restrict__ out) {
    __shared__ double sh[256];
    const int tid = threadIdx.x;
    double s = 0.0;
    for (int i = tid; i < NBLK; i += 256) s += g_partials[i];  // fixed order
    sh[tid] = s;
    __syncthreads();
    for (int off = 128; off; off >>= 1) {
        if (tid < off) sh[tid] += sh[tid + off];
        __syncthreads();
    }
    if (tid == 0) out[0] = (float)(sh[0] / (double)BATCH);
}

// ---------------- launch ----------------

extern "C" void kernel_launch(void* const* d_in, const int* in_sizes, int n_in,
                              void* d_out, int out_size) {
    (void)in_sizes; (void)n_in; (void)out_size;
    const float* v_data = (const float*)d_in[0];
    const float* kern   = (const float*)d_in[1];
    const float* bsc    = (const float*)d_in[2];
    const float* cvec   = (const float*)d_in[3];

    // JAX key schedule: key(42)=(0,42); fold-like split: keys[i]=threefry(k,(0,i))
    GibbsKeys keys;
    uint32_t k0 = 0u, k1 = 42u;
    for (int t = 0; t < KSTEPS; t++) {
        uint32_t n0, n1, h0, h1, w0, w1;
        tf2x32_host(k0, k1, 0u, 0u, &n0, &n1);
        tf2x32_host(k0, k1, 0u, 1u, &h0, &h1);
        tf2x32_host(k0, k1, 0u, 2u, &w0, &w1);
        keys.kh0[t] = h0; keys.kh1[t] = h1;
        keys.kv0[t] = w0; keys.kv1[t] = w1;
        k0 = n0; k1 = n1;
    }

    cudaFuncSetAttribute(rbm_kernel, cudaFuncAttributeMaxDynamicSharedMemorySize, SMEM_BYTES);
    rbm_kernel<<<NBLK, TPB, SMEM_BYTES>>>(v_data, kern, bsc, cvec, keys);
    reduce_kernel<<<1, 256>>>((float*)d_out);
}